// round 5
// baseline (speedup 1.0000x reference)
#include <cuda_runtime.h>
#include <cstdint>

#define N 4096
#define D 128

// ---------------- device globals (scratch; no allocations allowed) ----------------
__device__ __align__(16) float g_en[N * D];   // normalized embeddings
__device__ float g_tsorted[N];                // sorted targets
__device__ unsigned char g_low[N];
__device__ unsigned g_rowMinPos[N];  // encoded min-dot over positive mask (per anchor)
__device__ unsigned g_rowMaxNeg[N];  // encoded max-dot over negative mask (per anchor)
__device__ unsigned g_actReady;      // 0 = not ready, else float bits of actT
__device__ unsigned g_done;          // finished tile-block counter

// order-preserving float <-> uint encode
__device__ __forceinline__ unsigned encodeF(float f) {
    unsigned u = __float_as_uint(f);
    return (u & 0x80000000u) ? ~u : (u | 0x80000000u);
}
__device__ __forceinline__ float decodeF(unsigned u) {
    return (u & 0x80000000u) ? __uint_as_float(u & 0x7FFFFFFFu)
                             : __uint_as_float(~u);
}

// bitonic sort of s[N] in shared memory, 1024 threads
__device__ void bitonicSort(float* s) {
    int tid = threadIdx.x;
    for (int k = 2; k <= N; k <<= 1) {
        for (int j = k >> 1; j > 0; j >>= 1) {
            for (int idx = tid; idx < N; idx += 1024) {
                int p = idx ^ j;
                if (p > idx) {
                    float a = s[idx], b = s[p];
                    bool up = ((idx & k) == 0);
                    bool sw = up ? (a > b) : (a < b);
                    if (sw) { s[idx] = b; s[p] = a; }
                }
            }
            __syncthreads();
        }
    }
}

// ---------------- K1: fused init + normalize + sorts ----------------
__global__ void prepK(const float* __restrict__ emb, const float* __restrict__ au,
                      const float* __restrict__ tg) {
    __shared__ float s[N];
    __shared__ float thSh;
    int tid = threadIdx.x;  // 1024
    if (blockIdx.x < 128) {
        int row = blockIdx.x * 32 + (tid >> 5);
        int lane = tid & 31;
        const float4* p = (const float4*)(emb + (size_t)row * D);
        float4 v = p[lane];
        float ss = v.x * v.x + v.y * v.y + v.z * v.z + v.w * v.w;
#pragma unroll
        for (int st = 16; st > 0; st >>= 1) ss += __shfl_xor_sync(0xffffffffu, ss, st);
        float inv = 1.0f / fmaxf(sqrtf(ss), 1e-12f);
        float4 o;
        o.x = v.x * inv; o.y = v.y * inv; o.z = v.z * inv; o.w = v.w * inv;
        ((float4*)(g_en + (size_t)row * D))[lane] = o;
        return;
    }
    if (blockIdx.x == 128) {
        // init accumulators + sort aleatoric uncertainty -> median -> low mask
        for (int x = tid; x < N; x += 1024) {
            g_rowMinPos[x] = 0xFFFFFFFFu;
            g_rowMaxNeg[x] = 0u;
        }
        if (tid == 0) { g_actReady = 0u; g_done = 0u; }
        for (int i = tid; i < N; i += 1024) s[i] = au[i];
        __syncthreads();
        bitonicSort(s);
        if (tid == 0) thSh = 0.5f * s[2047] + 0.5f * s[2048];
        __syncthreads();
        float th = thSh;
        for (int i = tid; i < N; i += 1024) g_low[i] = (au[i] < th) ? 1 : 0;
        return;
    }
    // block 129: sort targets
    for (int i = tid; i < N; i += 1024) s[i] = tg[i];
    __syncthreads();
    bitonicSort(s);
    for (int i = tid; i < N; i += 1024) g_tsorted[i] = s[i];
}

// ---------------- block-wide (256 threads) reductions ----------------
__device__ unsigned blkSum256(unsigned v, volatile unsigned* redS) {
    int tid = threadIdx.x, lane = tid & 31, wid = tid >> 5;
#pragma unroll
    for (int s = 16; s > 0; s >>= 1) v += __shfl_xor_sync(0xffffffffu, v, s);
    if (lane == 0) redS[wid] = v;
    __syncthreads();
    if (wid == 0) {
        unsigned w = (lane < 8) ? redS[lane] : 0u;
#pragma unroll
        for (int s = 4; s > 0; s >>= 1) w += __shfl_xor_sync(0xffffffffu, w, s);
        if (lane == 0) redS[0] = w;
    }
    __syncthreads();
    unsigned r = redS[0];
    __syncthreads();
    return r;
}
__device__ unsigned blkMin256(unsigned v, volatile unsigned* redS) {
    int tid = threadIdx.x, lane = tid & 31, wid = tid >> 5;
#pragma unroll
    for (int s = 16; s > 0; s >>= 1) v = min(v, __shfl_xor_sync(0xffffffffu, v, s));
    if (lane == 0) redS[wid] = v;
    __syncthreads();
    if (wid == 0) {
        unsigned w = (lane < 8) ? redS[lane] : 0xFFFFFFFFu;
#pragma unroll
        for (int s = 4; s > 0; s >>= 1) w = min(w, __shfl_xor_sync(0xffffffffu, w, s));
        if (lane == 0) redS[0] = w;
    }
    __syncthreads();
    unsigned r = redS[0];
    __syncthreads();
    return r;
}

// bracketed probe: for each owned row, find e = max j in [eLo,eHi] with ts[j]-ts[r] <= x
// (bracket invariant guarantees the answer lies in [eLo[r], eHi[r]]).
// 4-way interleaved chains to hide LDS latency. Returns this thread's partial count.
__device__ unsigned probeCnt(const float* ts, const unsigned short* eLo,
                             const unsigned short* eHi, unsigned short* eTmp,
                             float x, int tid) {
    unsigned c = 0;
#pragma unroll 1
    for (int g = 0; g < 4; g++) {
        int r[4], lo[4], hi[4];
        float tv[4];
#pragma unroll
        for (int q = 0; q < 4; q++) {
            r[q] = tid + 256 * (g * 4 + q);
            lo[q] = eLo[r[q]];
            hi[q] = eHi[r[q]];
            tv[q] = ts[r[q]];
        }
        bool done = false;
#pragma unroll 1
        while (!done) {
            done = true;
#pragma unroll
            for (int q = 0; q < 4; q++) {
                if (lo[q] < hi[q]) {
                    int m = (lo[q] + hi[q] + 1) >> 1;
                    if (ts[m] - tv[q] <= x) lo[q] = m; else hi[q] = m - 1;
                    if (lo[q] < hi[q]) done = false;
                }
            }
        }
#pragma unroll
        for (int q = 0; q < 4; q++) {
            eTmp[r[q]] = (unsigned short)lo[q];
            c += (unsigned)(lo[q] - r[q]);
        }
    }
    return c;
}

// ---------------- K2: fused [select block 0] + [symmetric GEMM tiles 1..528] + [last-block finish] ----------------
__global__ __launch_bounds__(256, 2) void fusedK(const float* __restrict__ t,
                                                 float* __restrict__ out, int out_size) {
    __shared__ __align__(16) float As[32][136];
    __shared__ __align__(16) float Bs[32][136];
    __shared__ __align__(16) unsigned sColBuf[2048];
    __shared__ unsigned redS[8];
    __shared__ unsigned sOld;

    int tid = threadIdx.x;

    if (blockIdx.x == 0) {
        // ======== select block: exact masked-quantile threshold ========
        float* ts = &As[0][0];                       // 4096 floats
        unsigned short* eLo = (unsigned short*)&Bs[0][0];
        unsigned short* eHi = eLo + 4096;
        unsigned short* eTmp = (unsigned short*)sColBuf;  // 4096 shorts

        for (int i = tid; i < N; i += 256) ts[i] = g_tsorted[i];
        __syncthreads();

        // probe x = 0: tie count z, initialize brackets
        unsigned c0 = 0;
#pragma unroll 1
        for (int k = 0; k < 16; k++) {
            int r = tid + 256 * k;
            float tv = ts[r];
            int lo = r, hi = N - 1;
#pragma unroll 1
            while (lo < hi) {
                int m = (lo + hi + 1) >> 1;
                if (ts[m] - tv <= 0.0f) lo = m; else hi = m - 1;
            }
            eLo[r] = (unsigned short)lo;
            eHi[r] = (unsigned short)(N - 1);
            c0 += (unsigned)(lo - r);
        }
        unsigned z = blkSum256(c0, redS);

        // jax fp32 rank arithmetic (uniform across threads)
        unsigned long long n = 16773120ull - 2ull * (unsigned long long)z;
        float nf = (float)(n - 1ull);
        float pos = 0.2f * nf;
        float lof = floorf(pos);
        float frac = pos - lof;
        unsigned flatLo = (unsigned)lof;
        unsigned flatHi = (frac > 0.0f) ? flatLo + 1u : flatLo;
        unsigned kLo = flatLo >> 1;
        unsigned kHi = flatHi >> 1;
        unsigned target = kLo + 1u + z;

        // bisection over float bit patterns for vlo (kLo-th nonzero pair diff)
        unsigned lov = 0u, hiv = 0x7F7FFFFFu;
#pragma unroll 1
        while (lov < hiv) {
            unsigned mid = (lov + hiv) >> 1;
            unsigned c = probeCnt(ts, eLo, eHi, eTmp, __uint_as_float(mid), tid);
            c = blkSum256(c, redS);
            if (c >= target) {
                hiv = mid;
                for (int k = 0; k < 16; k++) { int r = tid + 256 * k; eHi[r] = eTmp[r]; }
            } else {
                lov = mid + 1u;
                for (int k = 0; k < 16; k++) { int r = tid + 256 * k; eLo[r] = eTmp[r]; }
            }
        }
        unsigned vloB = hiv;

        // final probe at vlo (brackets are tight) -> cStar, window ends eTmp
        unsigned cS = probeCnt(ts, eLo, eHi, eTmp, __uint_as_float(vloB), tid);
        cS = blkSum256(cS, redS);

        unsigned vhiB;
        if (kHi == kLo || cS >= kLo + 2u + z) {
            vhiB = vloB;
        } else {
            // min diff strictly above vlo = min over rows of ts[e+1]-ts[r]
            unsigned mb = 0xFFFFFFFFu;
#pragma unroll 1
            for (int k = 0; k < 16; k++) {
                int r = tid + 256 * k;
                int e = eTmp[r];
                if (e + 1 < N) {
                    float d = ts[e + 1] - ts[r];
                    mb = min(mb, __float_as_uint(d));
                }
            }
            vhiB = blkMin256(mb, redS);
        }

        if (tid == 0) {
            float flo = __uint_as_float(vloB);
            float fhi = __uint_as_float(vhiB);
            float a = __fmul_rn(flo, 1.0f - frac);
            float b = __fmul_rn(fhi, frac);
            float actT = __fadd_rn(a, b);
            __threadfence();
            atomicExch(&g_actReady, __float_as_uint(actT));
        }
        return;
    }

    // ======== tile blocks: symmetric scalar-FFMA GEMM + masked reductions ========
    unsigned* sColMin = sColBuf;
    unsigned* sColMax = sColBuf + 1024;

    int b = blockIdx.x - 1;
    int bi = 0;
    while (b >= 32 - bi) { b -= 32 - bi; bi++; }
    int bj = bi + b;
    int ri = bi * 128, rj = bj * 128;

    int r0 = (tid >> 4) * 4;
    int c0 = (tid & 15) * 4;

    float acc[8][8];
#pragma unroll
    for (int r = 0; r < 8; r++)
#pragma unroll
        for (int c = 0; c < 8; c++) acc[r][c] = 0.0f;

    int lr = tid >> 1, lh = tid & 1;
    for (int kc = 0; kc < 4; kc++) {
        const float4* pa = (const float4*)(g_en + (size_t)(ri + lr) * D + kc * 32 + lh * 16);
        const float4* pb = (const float4*)(g_en + (size_t)(rj + lr) * D + kc * 32 + lh * 16);
        float4 a0 = pa[0], a1 = pa[1], a2 = pa[2], a3 = pa[3];
        float4 b0 = pb[0], b1 = pb[1], b2 = pb[2], b3 = pb[3];
        if (kc) __syncthreads();
        int kb = lh * 16;
        As[kb + 0][lr] = a0.x; As[kb + 1][lr] = a0.y; As[kb + 2][lr] = a0.z; As[kb + 3][lr] = a0.w;
        As[kb + 4][lr] = a1.x; As[kb + 5][lr] = a1.y; As[kb + 6][lr] = a1.z; As[kb + 7][lr] = a1.w;
        As[kb + 8][lr] = a2.x; As[kb + 9][lr] = a2.y; As[kb + 10][lr] = a2.z; As[kb + 11][lr] = a2.w;
        As[kb + 12][lr] = a3.x; As[kb + 13][lr] = a3.y; As[kb + 14][lr] = a3.z; As[kb + 15][lr] = a3.w;
        Bs[kb + 0][lr] = b0.x; Bs[kb + 1][lr] = b0.y; Bs[kb + 2][lr] = b0.z; Bs[kb + 3][lr] = b0.w;
        Bs[kb + 4][lr] = b1.x; Bs[kb + 5][lr] = b1.y; Bs[kb + 6][lr] = b1.z; Bs[kb + 7][lr] = b1.w;
        Bs[kb + 8][lr] = b2.x; Bs[kb + 9][lr] = b2.y; Bs[kb + 10][lr] = b2.z; Bs[kb + 11][lr] = b2.w;
        Bs[kb + 12][lr] = b3.x; Bs[kb + 13][lr] = b3.y; Bs[kb + 14][lr] = b3.z; Bs[kb + 15][lr] = b3.w;
        __syncthreads();
#pragma unroll 8
        for (int k = 0; k < 32; k++) {
            float4 x0 = *(const float4*)&As[k][r0];
            float4 x1 = *(const float4*)&As[k][64 + r0];
            float4 y0 = *(const float4*)&Bs[k][c0];
            float4 y1 = *(const float4*)&Bs[k][64 + c0];
            float a[8] = {x0.x, x0.y, x0.z, x0.w, x1.x, x1.y, x1.z, x1.w};
            float bb[8] = {y0.x, y0.y, y0.z, y0.w, y1.x, y1.y, y1.z, y1.w};
#pragma unroll
            for (int r = 0; r < 8; r++)
#pragma unroll
                for (int c = 0; c < 8; c++) acc[r][c] += a[r] * bb[c];
        }
    }

    // wait for select block's threshold (normally already published)
    unsigned ab;
    do {
        ab = *(volatile unsigned*)&g_actReady;
        if (ab == 0u) __nanosleep(64);
    } while (ab == 0u);
    float actT = __uint_as_float(ab);

    // ---- fused epilogue: masked min/max for BOTH row anchors and col anchors ----
    int rows[8], cols[8];
#pragma unroll
    for (int u = 0; u < 4; u++) {
        rows[u] = ri + r0 + u;
        rows[4 + u] = ri + 64 + r0 + u;
        cols[u] = rj + c0 + u;
        cols[4 + u] = rj + 64 + c0 + u;
    }
    float ti[8], tj[8];
    int li[8], lj[8];
#pragma unroll
    for (int u = 0; u < 8; u++) {
        ti[u] = t[rows[u]];
        tj[u] = t[cols[u]];
        li[u] = g_low[rows[u]];
        lj[u] = g_low[cols[u]];
    }
    float pMin[8], nMax[8], cMin[8], cMax[8];
#pragma unroll
    for (int u = 0; u < 8; u++) {
        pMin[u] = 3.402823466e38f; nMax[u] = -3.402823466e38f;
        cMin[u] = 3.402823466e38f; cMax[u] = -3.402823466e38f;
    }
#pragma unroll
    for (int r = 0; r < 8; r++) {
#pragma unroll
        for (int c = 0; c < 8; c++) {
            float ad = fabsf(ti[r] - tj[c]);
            if (ad < actT) {
                float dv = acc[r][c];
                bool neq = rows[r] != cols[c];
                if (lj[c]) { if (neq) pMin[r] = fminf(pMin[r], dv); }
                else nMax[r] = fmaxf(nMax[r], dv);
                if (li[r]) { if (neq) cMin[c] = fminf(cMin[c], dv); }
                else cMax[c] = fmaxf(cMax[c], dv);
            }
        }
    }
    // row side: reduce across 16-lane groups sharing the same rows
#pragma unroll
    for (int s = 8; s > 0; s >>= 1) {
#pragma unroll
        for (int r = 0; r < 8; r++) {
            pMin[r] = fminf(pMin[r], __shfl_down_sync(0xffffffffu, pMin[r], s, 16));
            nMax[r] = fmaxf(nMax[r], __shfl_down_sync(0xffffffffu, nMax[r], s, 16));
        }
    }
    if ((tid & 15) == 0) {
#pragma unroll
        for (int r = 0; r < 8; r++) {
            if (pMin[r] < 3.0e38f) atomicMin(&g_rowMinPos[rows[r]], encodeF(pMin[r]));
            if (nMax[r] > -3.0e38f) atomicMax(&g_rowMaxNeg[rows[r]], encodeF(nMax[r]));
        }
    }
    // col side: combine lane pairs (l, l^16), stage per-warp partials, then flush
    unsigned eMin[8], eMax[8];
#pragma unroll
    for (int u = 0; u < 8; u++) {
        eMin[u] = encodeF(cMin[u]);
        eMax[u] = encodeF(cMax[u]);
        eMin[u] = min(eMin[u], __shfl_xor_sync(0xffffffffu, eMin[u], 16));
        eMax[u] = max(eMax[u], __shfl_xor_sync(0xffffffffu, eMax[u], 16));
    }
    int wrp = tid >> 5;
    __syncthreads();   // acc reads done; reuse sColBuf
    if ((tid & 31) < 16) {
#pragma unroll
        for (int u = 0; u < 4; u++) {
            sColMin[wrp * 128 + c0 + u] = eMin[u];
            sColMin[wrp * 128 + 64 + c0 + u] = eMin[4 + u];
            sColMax[wrp * 128 + c0 + u] = eMax[u];
            sColMax[wrp * 128 + 64 + c0 + u] = eMax[4 + u];
        }
    }
    __syncthreads();
    if (tid < 128) {
        unsigned v = sColMin[tid];
#pragma unroll
        for (int w = 1; w < 8; w++) v = min(v, sColMin[w * 128 + tid]);
        if (v < 0xFF000000u) atomicMin(&g_rowMinPos[rj + tid], v);
    } else {
        int c = tid - 128;
        unsigned v = sColMax[c];
#pragma unroll
        for (int w = 1; w < 8; w++) v = max(v, sColMax[w * 128 + c]);
        if (v > 0x01000000u) atomicMax(&g_rowMaxNeg[rj + c], v);
    }

    // ---- completion: last tile block computes the final loss ----
    __threadfence();
    if (tid == 0) sOld = atomicAdd(&g_done, 1u);
    __syncthreads();
    if (sOld != 527u) return;

    float sum = 0.0f;
    unsigned cnt = 0u;
    for (int i = tid; i < N; i += 256) {
        if (__ldcg(&g_low[i]) == 0) continue;
        unsigned ep = __ldcg(&g_rowMinPos[i]);
        if (ep == 0xFFFFFFFFu) continue;  // no positive
        unsigned en = __ldcg(&g_rowMaxNeg[i]);
        if (en == 0u) continue;           // no negative
        float minDot = decodeF(ep);
        float maxDot = decodeF(en);
        float hp = sqrtf(fmaxf(2.0f - 2.0f * minDot, 1e-12f));
        float hn = sqrtf(fmaxf(2.0f - 2.0f * maxDot, 1e-12f));
        float tl = hp - hn + 0.5f;
        if (tl < 0.0f) tl = 0.0f;
        sum += tl;
        cnt++;
    }
    // block reduce (256 threads)
    int lane = tid & 31;
    int wid = tid >> 5;
#pragma unroll
    for (int s = 16; s > 0; s >>= 1) {
        sum += __shfl_down_sync(0xffffffffu, sum, s);
        cnt += __shfl_down_sync(0xffffffffu, cnt, s);
    }
    __syncthreads();
    float* fred = (float*)redS;
    if (lane == 0) { fred[wid] = sum; sColBuf[wid] = cnt; }
    __syncthreads();
    if (wid == 0) {
        float s2 = (lane < 8) ? fred[lane] : 0.0f;
        unsigned c2 = (lane < 8) ? sColBuf[lane] : 0u;
#pragma unroll
        for (int s = 4; s > 0; s >>= 1) {
            s2 += __shfl_down_sync(0xffffffffu, s2, s);
            c2 += __shfl_down_sync(0xffffffffu, c2, s);
        }
        if (lane == 0) out[0] = s2 / (float)(c2 > 0u ? c2 : 1u);
    }
    for (int i = tid; i < out_size; i += 256)
        if (i > 0) out[i] = 0.0f;
}

// ---------------- launch ----------------
extern "C" void kernel_launch(void* const* d_in, const int* in_sizes, int n_in,
                              void* d_out, int out_size) {
    const float* emb = (const float*)d_in[0];
    const float* tg = (const float*)d_in[1];
    const float* au = (const float*)d_in[2];
    float* out = (float*)d_out;

    prepK<<<130, 1024>>>(emb, au, tg);
    fusedK<<<529, 256>>>(tg, out, out_size);
}

// round 6
// speedup vs baseline: 1.2212x; 1.2212x over previous
#include <cuda_runtime.h>
#include <cstdint>

#define N 4096
#define D 128
#define SELB 128   // blocks in the cooperative select kernel

// ---------------- device globals (scratch; no allocations allowed) ----------------
__device__ __align__(16) float g_en[N * D];   // normalized embeddings
__device__ float g_tsorted[N];                // sorted targets
__device__ unsigned char g_low[N];
__device__ unsigned g_rowMinPos[N];  // encoded min-dot over positive mask (per anchor)
__device__ unsigned g_rowMaxNeg[N];  // encoded max-dot over negative mask (per anchor)
__device__ unsigned g_cnt[4 * 256];  // per-round candidate counts
__device__ unsigned g_cntZ;          // tie (zero-diff) ordered pair count
__device__ unsigned g_bar[8];        // grid barrier counters
__device__ unsigned g_minAbove;      // min diff bits strictly above vlo
__device__ float    g_actT;          // final activity threshold

// order-preserving float <-> uint encode
__device__ __forceinline__ unsigned encodeF(float f) {
    unsigned u = __float_as_uint(f);
    return (u & 0x80000000u) ? ~u : (u | 0x80000000u);
}
__device__ __forceinline__ float decodeF(unsigned u) {
    return (u & 0x80000000u) ? __uint_as_float(u & 0x7FFFFFFFu)
                             : __uint_as_float(~u);
}

// bitonic sort of s[N] in shared memory, 1024 threads
__device__ void bitonicSort(float* s) {
    int tid = threadIdx.x;
    for (int k = 2; k <= N; k <<= 1) {
        for (int j = k >> 1; j > 0; j >>= 1) {
            for (int idx = tid; idx < N; idx += 1024) {
                int p = idx ^ j;
                if (p > idx) {
                    float a = s[idx], b = s[p];
                    bool up = ((idx & k) == 0);
                    bool sw = up ? (a > b) : (a < b);
                    if (sw) { s[idx] = b; s[p] = a; }
                }
            }
            __syncthreads();
        }
    }
}

// ---------------- K1: fused init + normalize + sorts ----------------
__global__ void prepK(const float* __restrict__ emb, const float* __restrict__ au,
                      const float* __restrict__ tg) {
    __shared__ float s[N];
    __shared__ float thSh;
    int tid = threadIdx.x;  // 1024
    if (blockIdx.x < 128) {
        int row = blockIdx.x * 32 + (tid >> 5);
        int lane = tid & 31;
        const float4* p = (const float4*)(emb + (size_t)row * D);
        float4 v = p[lane];
        float ss = v.x * v.x + v.y * v.y + v.z * v.z + v.w * v.w;
#pragma unroll
        for (int st = 16; st > 0; st >>= 1) ss += __shfl_xor_sync(0xffffffffu, ss, st);
        float inv = 1.0f / fmaxf(sqrtf(ss), 1e-12f);
        float4 o;
        o.x = v.x * inv; o.y = v.y * inv; o.z = v.z * inv; o.w = v.w * inv;
        ((float4*)(g_en + (size_t)row * D))[lane] = o;
        return;
    }
    if (blockIdx.x == 128) {
        // init accumulators + sort aleatoric uncertainty -> median -> low mask
        for (int x = tid; x < N; x += 1024) {
            g_rowMinPos[x] = 0xFFFFFFFFu;
            g_rowMaxNeg[x] = 0u;
        }
        for (int x = tid; x < 4 * 256; x += 1024) g_cnt[x] = 0u;
        if (tid < 8) g_bar[tid] = 0u;
        if (tid == 0) { g_cntZ = 0u; g_minAbove = 0xFFFFFFFFu; }
        for (int i = tid; i < N; i += 1024) s[i] = au[i];
        __syncthreads();
        bitonicSort(s);
        if (tid == 0) thSh = 0.5f * s[2047] + 0.5f * s[2048];
        __syncthreads();
        float th = thSh;
        for (int i = tid; i < N; i += 1024) g_low[i] = (au[i] < th) ? 1 : 0;
        return;
    }
    // block 129: sort targets
    for (int i = tid; i < N; i += 1024) s[i] = tg[i];
    __syncthreads();
    bitonicSort(s);
    for (int i = tid; i < N; i += 1024) g_tsorted[i] = s[i];
}

// ---------------- cooperative select helpers ----------------
__device__ __forceinline__ void gridBar(int k) {
    __syncthreads();
    if (threadIdx.x == 0) {
        __threadfence();
        atomicAdd(&g_bar[k], 1u);
        while (*(volatile unsigned*)&g_bar[k] < (unsigned)SELB) __nanosleep(32);
    }
    __syncthreads();
}

// count, over rows [rbase, rbase+32), pairs j>i with fl(ts[j]-ts[i]) <= x
// 4-way interleaved binary searches (rows independent)
__device__ __forceinline__ unsigned countRowsF(const float* ts, int rbase, float x) {
    unsigned c = 0;
#pragma unroll 1
    for (int g = 0; g < 8; g++) {
        int r[4], lo[4], hi[4];
        float tv[4];
#pragma unroll
        for (int q = 0; q < 4; q++) {
            r[q] = rbase + g * 4 + q;
            lo[q] = r[q]; hi[q] = N - 1; tv[q] = ts[r[q]];
        }
        bool done = false;
#pragma unroll 1
        while (!done) {
            done = true;
#pragma unroll
            for (int q = 0; q < 4; q++) {
                if (lo[q] < hi[q]) {
                    int m = (lo[q] + hi[q] + 1) >> 1;
                    if (ts[m] - tv[q] <= x) lo[q] = m; else hi[q] = m - 1;
                    if (lo[q] < hi[q]) done = false;
                }
            }
        }
#pragma unroll
        for (int q = 0; q < 4; q++) c += (unsigned)(lo[q] - r[q]);
    }
    return c;
}

// single-row search: last j in [r, N-1] with ts[j] - ts[r] <= x
__device__ __forceinline__ int rowEnd(const float* ts, int r, float x) {
    int lo = r, hi = N - 1;
    float tv = ts[r];
#pragma unroll 1
    while (lo < hi) {
        int m = (lo + hi + 1) >> 1;
        if (ts[m] - tv <= x) lo = m; else hi = m - 1;
    }
    return lo;
}

// find min candidate index with cnt >= target in slab (uniform result)
__device__ __forceinline__ unsigned pickC(int slab, unsigned target, unsigned* sC1, int kMax) {
    int tid = threadIdx.x;
    if (tid == 0) *sC1 = 0xFFFFFFFFu;
    __syncthreads();
    if (tid < kMax) {
        unsigned c = *(volatile unsigned*)&g_cnt[slab * 256 + tid];
        if (c >= target) atomicMin(sC1, (unsigned)tid);
    }
    __syncthreads();
    unsigned r = *sC1;
    __syncthreads();
    return r;
}

// ---------------- K2: grid-parallel exact masked-quantile select ----------------
__global__ __launch_bounds__(256) void selectK() {
    __shared__ float ts[N];
    __shared__ unsigned sC1;
    int tid = threadIdx.x;
    int b = blockIdx.x;
    int rbase = b * 32;
    for (int i = tid; i < N; i += 256) ts[i] = g_tsorted[i];
    __syncthreads();

    // ---- round 1 (step 2^23) + tie count ----
    unsigned lo = 0u, step = 1u << 23;
    {
        unsigned vb = lo + (unsigned)(tid + 1) * step - 1u;
        if (vb > 0x7F7FFFFFu) vb = 0x7F7FFFFFu;   // clamp away inf/NaN patterns
        unsigned c = countRowsF(ts, rbase, __uint_as_float(vb));
        atomicAdd(&g_cnt[0 * 256 + tid], c);
        if (tid < 32) {
            int r = rbase + tid;
            unsigned zc = (unsigned)(rowEnd(ts, r, 0.0f) - r);
#pragma unroll
            for (int s = 16; s > 0; s >>= 1) zc += __shfl_xor_sync(0xffffffffu, zc, s);
            if (tid == 0 && zc) atomicAdd(&g_cntZ, zc);
        }
    }
    gridBar(0);

    // uniform rank arithmetic (jax fp32-exact)
    unsigned z = *(volatile unsigned*)&g_cntZ;
    unsigned long long n = 16773120ull - 2ull * (unsigned long long)z;
    float nf = (float)(n - 1ull);
    float pos = 0.2f * nf;
    float lof = floorf(pos);
    float frac = pos - lof;
    unsigned flatLo = (unsigned)lof;
    unsigned flatHi = (frac > 0.0f) ? flatLo + 1u : flatLo;
    unsigned kLo = flatLo >> 1;
    unsigned kHi = flatHi >> 1;
    unsigned target = kLo + 1u + z;

    unsigned c1 = pickC(0, target, &sC1, 256);
    lo += c1 * step;
    step >>= 8;   // 2^15

    // ---- rounds 2, 3 ----
#pragma unroll 1
    for (int rd = 1; rd <= 2; rd++) {
        unsigned vb = lo + (unsigned)(tid + 1) * step - 1u;
        unsigned c = countRowsF(ts, rbase, __uint_as_float(vb));
        atomicAdd(&g_cnt[rd * 256 + tid], c);
        gridBar(rd);
        c1 = pickC(rd, target, &sC1, 256);
        lo += c1 * step;
        step >>= 8;   // -> 2^7 after rd=2
    }

    // ---- round 4: 128 candidates, step 1 -> exact vlo ----
    if (tid < 128) {
        unsigned vb = lo + (unsigned)tid;
        unsigned c = countRowsF(ts, rbase, __uint_as_float(vb));
        atomicAdd(&g_cnt[3 * 256 + tid], c);
    }
    gridBar(3);
    c1 = pickC(3, target, &sC1, 128);
    unsigned vloB = lo + c1;
    unsigned cntVlo = *(volatile unsigned*)&g_cnt[3 * 256 + c1];

    // ---- vhi ----
    bool same = (kHi == kLo) || (cntVlo >= kHi + 1u + z);
    if (!same && tid < 32) {
        int r = rbase + tid;
        int e = rowEnd(ts, r, __uint_as_float(vloB));
        if (e + 1 < N) {
            unsigned d = __float_as_uint(ts[e + 1] - ts[r]);
            atomicMin(&g_minAbove, d);
        }
    }
    gridBar(4);
    if (b == 0 && tid == 0) {
        unsigned vhiB = same ? vloB : *(volatile unsigned*)&g_minAbove;
        float flo = __uint_as_float(vloB);
        float fhi = __uint_as_float(vhiB);
        g_actT = __fadd_rn(__fmul_rn(flo, 1.0f - frac), __fmul_rn(fhi, frac));
    }
}

// ---------------- K3: zero out[1..] (also makes gemm the 4th launch for ncu) ----------------
__global__ void zeroOutK(float* __restrict__ out, int out_size) {
    int i = blockIdx.x * blockDim.x + threadIdx.x;
    if (i > 0 && i < out_size) out[i] = 0.0f;
}

// ---------------- K4: symmetric scalar-FFMA GEMM + fused masked row/col reductions ----------------
__global__ __launch_bounds__(256) void gemmMaskK(const float* __restrict__ t) {
    __shared__ __align__(16) float As[32][136];
    __shared__ __align__(16) float Bs[32][136];
    __shared__ unsigned sColMin[8][128];
    __shared__ unsigned sColMax[8][128];

    int tid = threadIdx.x;
    // triangular block mapping: bi <= bj over 32x32 tiles (528 blocks)
    int b = blockIdx.x;
    int bi = 0;
    while (b >= 32 - bi) { b -= 32 - bi; bi++; }
    int bj = bi + b;
    int ri = bi * 128, rj = bj * 128;

    int r0 = (tid >> 4) * 4;
    int c0 = (tid & 15) * 4;

    float acc[8][8];
#pragma unroll
    for (int r = 0; r < 8; r++)
#pragma unroll
        for (int c = 0; c < 8; c++) acc[r][c] = 0.0f;

    int lr = tid >> 1, lh = tid & 1;
    for (int kc = 0; kc < 4; kc++) {
        const float4* pa = (const float4*)(g_en + (size_t)(ri + lr) * D + kc * 32 + lh * 16);
        const float4* pb = (const float4*)(g_en + (size_t)(rj + lr) * D + kc * 32 + lh * 16);
        float4 a0 = pa[0], a1 = pa[1], a2 = pa[2], a3 = pa[3];
        float4 b0 = pb[0], b1 = pb[1], b2 = pb[2], b3 = pb[3];
        if (kc) __syncthreads();
        int kb = lh * 16;
        As[kb + 0][lr] = a0.x; As[kb + 1][lr] = a0.y; As[kb + 2][lr] = a0.z; As[kb + 3][lr] = a0.w;
        As[kb + 4][lr] = a1.x; As[kb + 5][lr] = a1.y; As[kb + 6][lr] = a1.z; As[kb + 7][lr] = a1.w;
        As[kb + 8][lr] = a2.x; As[kb + 9][lr] = a2.y; As[kb + 10][lr] = a2.z; As[kb + 11][lr] = a2.w;
        As[kb + 12][lr] = a3.x; As[kb + 13][lr] = a3.y; As[kb + 14][lr] = a3.z; As[kb + 15][lr] = a3.w;
        Bs[kb + 0][lr] = b0.x; Bs[kb + 1][lr] = b0.y; Bs[kb + 2][lr] = b0.z; Bs[kb + 3][lr] = b0.w;
        Bs[kb + 4][lr] = b1.x; Bs[kb + 5][lr] = b1.y; Bs[kb + 6][lr] = b1.z; Bs[kb + 7][lr] = b1.w;
        Bs[kb + 8][lr] = b2.x; Bs[kb + 9][lr] = b2.y; Bs[kb + 10][lr] = b2.z; Bs[kb + 11][lr] = b2.w;
        Bs[kb + 12][lr] = b3.x; Bs[kb + 13][lr] = b3.y; Bs[kb + 14][lr] = b3.z; Bs[kb + 15][lr] = b3.w;
        __syncthreads();
#pragma unroll 8
        for (int k = 0; k < 32; k++) {
            float4 x0 = *(const float4*)&As[k][r0];
            float4 x1 = *(const float4*)&As[k][64 + r0];
            float4 y0 = *(const float4*)&Bs[k][c0];
            float4 y1 = *(const float4*)&Bs[k][64 + c0];
            float a[8] = {x0.x, x0.y, x0.z, x0.w, x1.x, x1.y, x1.z, x1.w};
            float bb[8] = {y0.x, y0.y, y0.z, y0.w, y1.x, y1.y, y1.z, y1.w};
#pragma unroll
            for (int r = 0; r < 8; r++)
#pragma unroll
                for (int c = 0; c < 8; c++) acc[r][c] += a[r] * bb[c];
        }
    }

    float actT = g_actT;

    // ---- fused epilogue: masked min/max for BOTH row anchors and col anchors ----
    int rows[8], cols[8];
#pragma unroll
    for (int u = 0; u < 4; u++) {
        rows[u] = ri + r0 + u;
        rows[4 + u] = ri + 64 + r0 + u;
        cols[u] = rj + c0 + u;
        cols[4 + u] = rj + 64 + c0 + u;
    }
    float ti[8], tj[8];
    int li[8], lj[8];
#pragma unroll
    for (int u = 0; u < 8; u++) {
        ti[u] = t[rows[u]];
        tj[u] = t[cols[u]];
        li[u] = g_low[rows[u]];
        lj[u] = g_low[cols[u]];
    }
    float pMin[8], nMax[8], cMin[8], cMax[8];
#pragma unroll
    for (int u = 0; u < 8; u++) {
        pMin[u] = 3.402823466e38f; nMax[u] = -3.402823466e38f;
        cMin[u] = 3.402823466e38f; cMax[u] = -3.402823466e38f;
    }
#pragma unroll
    for (int r = 0; r < 8; r++) {
#pragma unroll
        for (int c = 0; c < 8; c++) {
            float ad = fabsf(ti[r] - tj[c]);
            if (ad < actT) {
                float dv = acc[r][c];
                bool neq = rows[r] != cols[c];
                if (lj[c]) { if (neq) pMin[r] = fminf(pMin[r], dv); }
                else nMax[r] = fmaxf(nMax[r], dv);
                if (li[r]) { if (neq) cMin[c] = fminf(cMin[c], dv); }
                else cMax[c] = fmaxf(cMax[c], dv);
            }
        }
    }
    // row side: reduce across 16-lane groups sharing the same rows
#pragma unroll
    for (int s = 8; s > 0; s >>= 1) {
#pragma unroll
        for (int r = 0; r < 8; r++) {
            pMin[r] = fminf(pMin[r], __shfl_down_sync(0xffffffffu, pMin[r], s, 16));
            nMax[r] = fmaxf(nMax[r], __shfl_down_sync(0xffffffffu, nMax[r], s, 16));
        }
    }
    if ((tid & 15) == 0) {
#pragma unroll
        for (int r = 0; r < 8; r++) {
            if (pMin[r] < 3.0e38f) atomicMin(&g_rowMinPos[rows[r]], encodeF(pMin[r]));
            if (nMax[r] > -3.0e38f) atomicMax(&g_rowMaxNeg[rows[r]], encodeF(nMax[r]));
        }
    }
    // col side: combine lane pairs (l, l^16), stage per-warp partials, then flush
    unsigned eMin[8], eMax[8];
#pragma unroll
    for (int u = 0; u < 8; u++) {
        eMin[u] = encodeF(cMin[u]);
        eMax[u] = encodeF(cMax[u]);
        eMin[u] = min(eMin[u], __shfl_xor_sync(0xffffffffu, eMin[u], 16));
        eMax[u] = max(eMax[u], __shfl_xor_sync(0xffffffffu, eMax[u], 16));
    }
    int wrp = tid >> 5;
    if ((tid & 31) < 16) {
#pragma unroll
        for (int u = 0; u < 4; u++) {
            sColMin[wrp][c0 + u] = eMin[u];
            sColMin[wrp][64 + c0 + u] = eMin[4 + u];
            sColMax[wrp][c0 + u] = eMax[u];
            sColMax[wrp][64 + c0 + u] = eMax[4 + u];
        }
    }
    __syncthreads();
    if (tid < 128) {
        unsigned v = sColMin[0][tid];
#pragma unroll
        for (int w = 1; w < 8; w++) v = min(v, sColMin[w][tid]);
        if (v < 0xFF000000u) atomicMin(&g_rowMinPos[rj + tid], v);
    } else if (tid < 256) {
        int c = tid - 128;
        unsigned v = sColMax[0][c];
#pragma unroll
        for (int w = 1; w < 8; w++) v = max(v, sColMax[w][c]);
        if (v > 0x01000000u) atomicMax(&g_rowMaxNeg[rj + c], v);
    }
}

// ---------------- K5: per-anchor loss + mean ----------------
__global__ void finalK(float* __restrict__ out) {
    __shared__ float sSum[32];
    __shared__ unsigned sCnt[32];
    int tid = threadIdx.x;  // 1024
    int lane = tid & 31, wid = tid >> 5;
    float sum = 0.0f;
    unsigned cnt = 0u;
    for (int i = tid; i < N; i += 1024) {
        if (!g_low[i]) continue;
        unsigned ep = g_rowMinPos[i];
        if (ep == 0xFFFFFFFFu) continue;  // no positive
        unsigned en = g_rowMaxNeg[i];
        if (en == 0u) continue;           // no negative
        float minDot = decodeF(ep);
        float maxDot = decodeF(en);
        float hp = sqrtf(fmaxf(2.0f - 2.0f * minDot, 1e-12f));
        float hn = sqrtf(fmaxf(2.0f - 2.0f * maxDot, 1e-12f));
        float tl = hp - hn + 0.5f;
        if (tl < 0.0f) tl = 0.0f;
        sum += tl;
        cnt++;
    }
#pragma unroll
    for (int s = 16; s > 0; s >>= 1) {
        sum += __shfl_down_sync(0xffffffffu, sum, s);
        cnt += __shfl_down_sync(0xffffffffu, cnt, s);
    }
    if (lane == 0) { sSum[wid] = sum; sCnt[wid] = cnt; }
    __syncthreads();
    if (wid == 0) {
        float s2 = sSum[lane];
        unsigned c2 = sCnt[lane];
#pragma unroll
        for (int s = 16; s > 0; s >>= 1) {
            s2 += __shfl_down_sync(0xffffffffu, s2, s);
            c2 += __shfl_down_sync(0xffffffffu, c2, s);
        }
        if (lane == 0) out[0] = s2 / (float)(c2 > 0u ? c2 : 1u);
    }
}

// ---------------- launch ----------------
extern "C" void kernel_launch(void* const* d_in, const int* in_sizes, int n_in,
                              void* d_out, int out_size) {
    const float* emb = (const float*)d_in[0];
    const float* tg = (const float*)d_in[1];
    const float* au = (const float*)d_in[2];
    float* out = (float*)d_out;

    prepK<<<130, 1024>>>(emb, au, tg);                          // launch 1
    selectK<<<SELB, 256>>>();                                   // launch 2
    zeroOutK<<<(unsigned)((out_size + 255) / 256), 256>>>(out, out_size);  // launch 3
    gemmMaskK<<<528, 256>>>(tg);                                // launch 4  (ncu captures this)
    finalK<<<1, 1024>>>(out);                                   // launch 5
}

// round 8
// speedup vs baseline: 1.8681x; 1.5297x over previous
#include <cuda_runtime.h>
#include <cstdint>

#define N 4096
#define D 128

// ---------------- device globals (scratch; no allocations allowed) ----------------
__device__ __align__(16) float g_en[N * D];   // normalized embeddings
__device__ unsigned char g_low[N];
__device__ unsigned g_rowMinPos[N];  // encoded min-dot over positive mask (per anchor)
__device__ unsigned g_rowMaxNeg[N];  // encoded max-dot over negative mask (per anchor)
__device__ unsigned g_hist1[4096];
__device__ unsigned g_hist2[4096];
__device__ unsigned g_hist3[256];
__device__ unsigned g_zeroPairs;
__device__ unsigned g_vloBits;
__device__ unsigned g_sameFlag;
__device__ float    g_frac;
__device__ unsigned g_minAbove;

// order-preserving float <-> uint encode
__device__ __forceinline__ unsigned encodeF(float f) {
    unsigned u = __float_as_uint(f);
    return (u & 0x80000000u) ? ~u : (u | 0x80000000u);
}
__device__ __forceinline__ float decodeF(unsigned u) {
    return (u & 0x80000000u) ? __uint_as_float(u & 0x7FFFFFFFu)
                             : __uint_as_float(~u);
}

// jax fp32-exact rank arithmetic (uniform across threads)
__device__ __forceinline__ void rankMath(unsigned z, unsigned& mLo, unsigned& mHi, float& frac) {
    unsigned long long n = 16773120ull - 2ull * (unsigned long long)z;
    float nf = (float)(n - 1ull);          // (n-1).astype(float32)
    float pos = 0.2f * nf;                 // q * (n-1)  [fp32!]
    float lof = floorf(pos);
    frac = pos - lof;
    unsigned fl = (unsigned)lof;
    mLo = fl >> 1;                         // flat rank -> unordered-pair rank
    mHi = (fl + 1u) >> 1;
}

// ---- locate rank in a 4096-bin histogram; 256-thread block ----
__device__ void locate4096_b256(const unsigned* gh, unsigned rank,
                                volatile unsigned* wS,
                                volatile unsigned* outBin, volatile unsigned* outRem) {
    int tid = threadIdx.x, lane = tid & 31, wid = tid >> 5;
    unsigned hl[16];
    unsigned lsum = 0;
#pragma unroll
    for (int k = 0; k < 16; k++) { hl[k] = gh[tid * 16 + k]; lsum += hl[k]; }
    unsigned v = lsum;
#pragma unroll
    for (int s = 1; s < 32; s <<= 1) {
        unsigned o = __shfl_up_sync(0xffffffffu, v, s);
        if (lane >= s) v += o;
    }
    if (lane == 31) wS[wid] = v;
    __syncthreads();
    if (tid == 0) { unsigned run = 0; for (int w = 0; w < 8; w++) { run += wS[w]; wS[w] = run; } }
    __syncthreads();
    unsigned cum = (v - lsum) + (wid ? wS[wid - 1] : 0u);
#pragma unroll
    for (int k = 0; k < 16; k++) {
        unsigned h = hl[k];
        if (h && rank >= cum && rank < cum + h) { *outBin = (unsigned)(tid * 16 + k); *outRem = rank - cum; }
        cum += h;
    }
    __syncthreads();
}

// ---- locate rank in a 256-bin histogram (with bin count); 256-thread block ----
__device__ void locate256_b256(const unsigned* gh, unsigned rank,
                               volatile unsigned* wS,
                               volatile unsigned* outBin, volatile unsigned* outRem,
                               volatile unsigned* outCnt) {
    int tid = threadIdx.x, lane = tid & 31, wid = tid >> 5;
    unsigned h = gh[tid];
    unsigned v = h;
#pragma unroll
    for (int s = 1; s < 32; s <<= 1) {
        unsigned o = __shfl_up_sync(0xffffffffu, v, s);
        if (lane >= s) v += o;
    }
    if (lane == 31) wS[wid] = v;
    __syncthreads();
    if (tid == 0) { unsigned run = 0; for (int w = 0; w < 8; w++) { run += wS[w]; wS[w] = run; } }
    __syncthreads();
    unsigned cum = (v - h) + (wid ? wS[wid - 1] : 0u);
    if (h && rank >= cum && rank < cum + h) { *outBin = (unsigned)tid; *outRem = rank - cum; *outCnt = h; }
    __syncthreads();
}

// ---- locate rank in 4096-bin shared hist; 1024-thread block (for prep median) ----
__device__ void locate4096_b1024(const unsigned* h, unsigned rank,
                                 volatile unsigned* wS,
                                 volatile unsigned* outBin, volatile unsigned* outRem) {
    int tid = threadIdx.x, lane = tid & 31, wid = tid >> 5;
    unsigned hl[4];
    unsigned lsum = 0;
#pragma unroll
    for (int k = 0; k < 4; k++) { hl[k] = h[tid * 4 + k]; lsum += hl[k]; }
    unsigned v = lsum;
#pragma unroll
    for (int s = 1; s < 32; s <<= 1) {
        unsigned o = __shfl_up_sync(0xffffffffu, v, s);
        if (lane >= s) v += o;
    }
    if (lane == 31) wS[wid] = v;
    __syncthreads();
    if (tid == 0) { unsigned run = 0; for (int w = 0; w < 32; w++) { run += wS[w]; wS[w] = run; } }
    __syncthreads();
    unsigned cum = (v - lsum) + (wid ? wS[wid - 1] : 0u);
#pragma unroll
    for (int k = 0; k < 4; k++) {
        unsigned hh = hl[k];
        if (hh && rank >= cum && rank < cum + hh) { *outBin = (unsigned)(tid * 4 + k); *outRem = rank - cum; }
        cum += hh;
    }
    __syncthreads();
}

// ---------------- K1: init + normalize + exact au-median (radix select) ----------------
__global__ void prepK(const float* __restrict__ emb, const float* __restrict__ au) {
    __shared__ unsigned e[4096];
    __shared__ unsigned h[4096];
    __shared__ unsigned wS[32];
    __shared__ unsigned sB, sR;
    int tid = threadIdx.x;  // 1024
    if (blockIdx.x < 128) {
        int row = blockIdx.x * 32 + (tid >> 5);
        int lane = tid & 31;
        const float4* p = (const float4*)(emb + (size_t)row * D);
        float4 v = p[lane];
        float ss = v.x * v.x + v.y * v.y + v.z * v.z + v.w * v.w;
#pragma unroll
        for (int st = 16; st > 0; st >>= 1) ss += __shfl_xor_sync(0xffffffffu, ss, st);
        float inv = 1.0f / fmaxf(sqrtf(ss), 1e-12f);
        float4 o;
        o.x = v.x * inv; o.y = v.y * inv; o.z = v.z * inv; o.w = v.w * inv;
        ((float4*)(g_en + (size_t)row * D))[lane] = o;
        return;
    }
    // block 128: init globals + median of au via 3-level radix select (ranks 2047, 2048)
    for (int x = tid; x < 4096; x += 1024) {
        g_rowMinPos[x] = 0xFFFFFFFFu;
        g_rowMaxNeg[x] = 0u;
        g_hist1[x] = 0u;
        g_hist2[x] = 0u;
    }
    for (int x = tid; x < 256; x += 1024) g_hist3[x] = 0u;
    if (tid == 0) { g_zeroPairs = 0u; g_minAbove = 0xFFFFFFFFu; }

    for (int i = tid; i < N; i += 1024) e[i] = encodeF(au[i]);
    __syncthreads();

    float vals[2];
#pragma unroll 1
    for (int r = 0; r < 2; r++) {
        unsigned rank = 2047u + (unsigned)r;
        // level 1: top 12 bits
        for (int x = tid; x < 4096; x += 1024) h[x] = 0u;
        __syncthreads();
        for (int i = tid; i < N; i += 1024) atomicAdd(&h[e[i] >> 20], 1u);
        __syncthreads();
        locate4096_b1024(h, rank, wS, &sB, &sR);
        unsigned b1 = sB, r1 = sR;
        __syncthreads();
        // level 2: middle 12 bits
        for (int x = tid; x < 4096; x += 1024) h[x] = 0u;
        __syncthreads();
        for (int i = tid; i < N; i += 1024)
            if ((e[i] >> 20) == b1) atomicAdd(&h[(e[i] >> 8) & 0xFFFu], 1u);
        __syncthreads();
        locate4096_b1024(h, r1, wS, &sB, &sR);
        unsigned b2 = sB, r2 = sR;
        unsigned pfx = (b1 << 12) | b2;
        __syncthreads();
        // level 3: low 8 bits (zero full 4096 so locate4096 works unchanged)
        for (int x = tid; x < 4096; x += 1024) h[x] = 0u;
        __syncthreads();
        for (int i = tid; i < N; i += 1024)
            if ((e[i] >> 8) == pfx) atomicAdd(&h[e[i] & 0xFFu], 1u);
        __syncthreads();
        locate4096_b1024(h, r2, wS, &sB, &sR);
        unsigned b3 = sB;
        __syncthreads();
        vals[r] = decodeF((b1 << 20) | (b2 << 8) | b3);
    }
    float th = __fadd_rn(__fmul_rn(vals[0], 0.5f), __fmul_rn(vals[1], 0.5f));
    for (int i = tid; i < N; i += 1024) g_low[i] = (au[i] < th) ? 1 : 0;
}

// ---------------- hist passes over unordered pairs (float4-vectorized) ----------------
template <int PASS>
__global__ __launch_bounds__(256) void histP(const float* __restrict__ t) {
    __shared__ __align__(16) float4 tsv4[1024];
    __shared__ unsigned hist[4096];
    __shared__ unsigned wS[8];
    __shared__ unsigned sB1, sR1, sB2, sR2, sB3, sR3, sC3;
    __shared__ unsigned sAgg;   // PASS1: zero-pair count; PASS4: block min (init differs!)
    int tid = threadIdx.x;  // 256
    const float* tss = (const float*)tsv4;

    for (int k = tid; k < 1024; k += 256) tsv4[k] = ((const float4*)t)[k];
    if (PASS <= 2) { for (int x = tid; x < 4096; x += 256) hist[x] = 0u; }
    if (PASS == 3) { for (int x = tid; x < 256; x += 256) hist[x] = 0u; }
    if (tid == 0) sAgg = (PASS == 4) ? 0xFFFFFFFFu : 0u;
    __syncthreads();

    // ---- prologue: derive filter parameters from previous passes' global hists ----
    unsigned p1 = 0, pfx24 = 0, vlo = 0;
    if (PASS >= 2) {
        unsigned z = g_zeroPairs;
        unsigned mLo, mHi; float frac;
        rankMath(z, mLo, mHi, frac);
        locate4096_b256(g_hist1, mLo, wS, &sB1, &sR1);
        p1 = sB1;
        unsigned r1 = sR1;
        __syncthreads();
        if (PASS >= 3) {
            locate4096_b256(g_hist2, r1, wS, &sB2, &sR2);
            pfx24 = (p1 << 12) | sB2;
            unsigned r2 = sR2;
            __syncthreads();
            if (PASS == 4) {
                locate256_b256(g_hist3, r2, wS, &sB3, &sR3, &sC3);
                vlo = (pfx24 << 8) | sB3;
                unsigned rem3 = sR3, cnt3 = sC3;
                __syncthreads();
                if (tid == 0) {
                    unsigned same = (mHi == mLo || rem3 + 1u < cnt3) ? 1u : 0u;
                    g_vloBits = vlo;
                    g_sameFlag = same;
                    g_frac = frac;
                }
            }
        }
    }

    // ---- main pair loop (rows strided by block; j vectorized in float4) ----
    unsigned zc = 0u;
    unsigned myMin = 0xFFFFFFFFu;
    for (int i = blockIdx.x; i < N; i += gridDim.x) {
        float ti = tss[i];
        int v0 = (i + 1) >> 2;
        for (int v = v0 + tid; v < 1024; v += 256) {
            float4 w = tsv4[v];
            int jb = v << 2;
#pragma unroll
            for (int k = 0; k < 4; k++) {
                float tj = (k == 0) ? w.x : (k == 1) ? w.y : (k == 2) ? w.z : w.w;
                if (jb + k > i) {
                    unsigned b = __float_as_uint(fabsf(ti - tj));
                    if (PASS == 1) {
                        if (b == 0u) zc++;
                        else atomicAdd(&hist[b >> 20], 1u);
                    } else if (PASS == 2) {
                        if (b != 0u && (b >> 20) == p1) atomicAdd(&hist[(b >> 8) & 0xFFFu], 1u);
                    } else if (PASS == 3) {
                        if (b != 0u && (b >> 8) == pfx24) atomicAdd(&hist[b & 0xFFu], 1u);
                    } else {
                        if (b > vlo) myMin = min(myMin, b);
                    }
                }
            }
        }
    }
    __syncthreads();

    // ---- flush ----
    if (PASS == 1) {
        for (int x = tid; x < 4096; x += 256)
            if (hist[x]) atomicAdd(&g_hist1[x], hist[x]);
#pragma unroll
        for (int s = 16; s > 0; s >>= 1) zc += __shfl_xor_sync(0xffffffffu, zc, s);
        if ((tid & 31) == 0 && zc) atomicAdd(&sAgg, zc);
        __syncthreads();
        if (tid == 0 && sAgg) atomicAdd(&g_zeroPairs, sAgg);
    } else if (PASS == 2) {
        for (int x = tid; x < 4096; x += 256)
            if (hist[x]) atomicAdd(&g_hist2[x], hist[x]);
    } else if (PASS == 3) {
        if (tid < 256 && hist[tid]) atomicAdd(&g_hist3[tid], hist[tid]);
    } else {
#pragma unroll
        for (int s = 16; s > 0; s >>= 1) myMin = min(myMin, __shfl_xor_sync(0xffffffffu, myMin, s));
        if ((tid & 31) == 0) atomicMin(&sAgg, myMin);
        __syncthreads();
        if (tid == 0 && sAgg != 0xFFFFFFFFu) atomicMin(&g_minAbove, sAgg);
    }
}

// ---------------- K6: symmetric scalar-FFMA GEMM + fused masked row/col reductions ----------------
__global__ __launch_bounds__(256) void gemmMaskK(const float* __restrict__ t) {
    __shared__ __align__(16) float As[32][136];
    __shared__ __align__(16) float Bs[32][136];
    __shared__ unsigned sColMin[8][128];
    __shared__ unsigned sColMax[8][128];

    int tid = threadIdx.x;
    int b = blockIdx.x;
    int bi = 0;
    while (b >= 32 - bi) { b -= 32 - bi; bi++; }
    int bj = bi + b;
    int ri = bi * 128, rj = bj * 128;

    int r0 = (tid >> 4) * 4;
    int c0 = (tid & 15) * 4;

    float acc[8][8];
#pragma unroll
    for (int r = 0; r < 8; r++)
#pragma unroll
        for (int c = 0; c < 8; c++) acc[r][c] = 0.0f;

    int lr = tid >> 1, lh = tid & 1;
    for (int kc = 0; kc < 4; kc++) {
        const float4* pa = (const float4*)(g_en + (size_t)(ri + lr) * D + kc * 32 + lh * 16);
        const float4* pb = (const float4*)(g_en + (size_t)(rj + lr) * D + kc * 32 + lh * 16);
        float4 a0 = pa[0], a1 = pa[1], a2 = pa[2], a3 = pa[3];
        float4 b0 = pb[0], b1 = pb[1], b2 = pb[2], b3 = pb[3];
        if (kc) __syncthreads();
        int kb = lh * 16;
        As[kb + 0][lr] = a0.x; As[kb + 1][lr] = a0.y; As[kb + 2][lr] = a0.z; As[kb + 3][lr] = a0.w;
        As[kb + 4][lr] = a1.x; As[kb + 5][lr] = a1.y; As[kb + 6][lr] = a1.z; As[kb + 7][lr] = a1.w;
        As[kb + 8][lr] = a2.x; As[kb + 9][lr] = a2.y; As[kb + 10][lr] = a2.z; As[kb + 11][lr] = a2.w;
        As[kb + 12][lr] = a3.x; As[kb + 13][lr] = a3.y; As[kb + 14][lr] = a3.z; As[kb + 15][lr] = a3.w;
        Bs[kb + 0][lr] = b0.x; Bs[kb + 1][lr] = b0.y; Bs[kb + 2][lr] = b0.z; Bs[kb + 3][lr] = b0.w;
        Bs[kb + 4][lr] = b1.x; Bs[kb + 5][lr] = b1.y; Bs[kb + 6][lr] = b1.z; Bs[kb + 7][lr] = b1.w;
        Bs[kb + 8][lr] = b2.x; Bs[kb + 9][lr] = b2.y; Bs[kb + 10][lr] = b2.z; Bs[kb + 11][lr] = b2.w;
        Bs[kb + 12][lr] = b3.x; Bs[kb + 13][lr] = b3.y; Bs[kb + 14][lr] = b3.z; Bs[kb + 15][lr] = b3.w;
        __syncthreads();
#pragma unroll 8
        for (int k = 0; k < 32; k++) {
            float4 x0 = *(const float4*)&As[k][r0];
            float4 x1 = *(const float4*)&As[k][64 + r0];
            float4 y0 = *(const float4*)&Bs[k][c0];
            float4 y1 = *(const float4*)&Bs[k][64 + c0];
            float a[8] = {x0.x, x0.y, x0.z, x0.w, x1.x, x1.y, x1.z, x1.w};
            float bb[8] = {y0.x, y0.y, y0.z, y0.w, y1.x, y1.y, y1.z, y1.w};
#pragma unroll
            for (int r = 0; r < 8; r++)
#pragma unroll
                for (int c = 0; c < 8; c++) acc[r][c] += a[r] * bb[c];
        }
    }

    // act threshold from pass-4 scalars
    unsigned vloB = g_vloBits;
    float flo = __uint_as_float(vloB);
    float fhi = g_sameFlag ? flo : __uint_as_float(g_minAbove);
    float fr = g_frac;
    float actT = __fadd_rn(__fmul_rn(flo, 1.0f - fr), __fmul_rn(fhi, fr));

    int rows[8], cols[8];
#pragma unroll
    for (int u = 0; u < 4; u++) {
        rows[u] = ri + r0 + u;
        rows[4 + u] = ri + 64 + r0 + u;
        cols[u] = rj + c0 + u;
        cols[4 + u] = rj + 64 + c0 + u;
    }
    float ti[8], tj[8];
    int li[8], lj[8];
#pragma unroll
    for (int u = 0; u < 8; u++) {
        ti[u] = t[rows[u]];
        tj[u] = t[cols[u]];
        li[u] = g_low[rows[u]];
        lj[u] = g_low[cols[u]];
    }
    float pMin[8], nMax[8], cMin[8], cMax[8];
#pragma unroll
    for (int u = 0; u < 8; u++) {
        pMin[u] = 3.402823466e38f; nMax[u] = -3.402823466e38f;
        cMin[u] = 3.402823466e38f; cMax[u] = -3.402823466e38f;
    }
#pragma unroll
    for (int r = 0; r < 8; r++) {
#pragma unroll
        for (int c = 0; c < 8; c++) {
            float ad = fabsf(ti[r] - tj[c]);
            if (ad < actT) {
                float dv = acc[r][c];
                bool neq = rows[r] != cols[c];
                if (lj[c]) { if (neq) pMin[r] = fminf(pMin[r], dv); }
                else nMax[r] = fmaxf(nMax[r], dv);
                if (li[r]) { if (neq) cMin[c] = fminf(cMin[c], dv); }
                else cMax[c] = fmaxf(cMax[c], dv);
            }
        }
    }
#pragma unroll
    for (int s = 8; s > 0; s >>= 1) {
#pragma unroll
        for (int r = 0; r < 8; r++) {
            pMin[r] = fminf(pMin[r], __shfl_down_sync(0xffffffffu, pMin[r], s, 16));
            nMax[r] = fmaxf(nMax[r], __shfl_down_sync(0xffffffffu, nMax[r], s, 16));
        }
    }
    if ((tid & 15) == 0) {
#pragma unroll
        for (int r = 0; r < 8; r++) {
            if (pMin[r] < 3.0e38f) atomicMin(&g_rowMinPos[rows[r]], encodeF(pMin[r]));
            if (nMax[r] > -3.0e38f) atomicMax(&g_rowMaxNeg[rows[r]], encodeF(nMax[r]));
        }
    }
    unsigned eMin[8], eMax[8];
#pragma unroll
    for (int u = 0; u < 8; u++) {
        eMin[u] = encodeF(cMin[u]);
        eMax[u] = encodeF(cMax[u]);
        eMin[u] = min(eMin[u], __shfl_xor_sync(0xffffffffu, eMin[u], 16));
        eMax[u] = max(eMax[u], __shfl_xor_sync(0xffffffffu, eMax[u], 16));
    }
    int wrp = tid >> 5;
    if ((tid & 31) < 16) {
#pragma unroll
        for (int u = 0; u < 4; u++) {
            sColMin[wrp][c0 + u] = eMin[u];
            sColMin[wrp][64 + c0 + u] = eMin[4 + u];
            sColMax[wrp][c0 + u] = eMax[u];
            sColMax[wrp][64 + c0 + u] = eMax[4 + u];
        }
    }
    __syncthreads();
    if (tid < 128) {
        unsigned v = sColMin[0][tid];
#pragma unroll
        for (int w = 1; w < 8; w++) v = min(v, sColMin[w][tid]);
        if (v < 0xFF000000u) atomicMin(&g_rowMinPos[rj + tid], v);
    } else if (tid < 256) {
        int c = tid - 128;
        unsigned v = sColMax[0][c];
#pragma unroll
        for (int w = 1; w < 8; w++) v = max(v, sColMax[w][c]);
        if (v > 0x01000000u) atomicMax(&g_rowMaxNeg[rj + c], v);
    }
}

// ---------------- K7: per-anchor loss + mean ----------------
__global__ void finalK(float* __restrict__ out, int out_size) {
    __shared__ float sSum[32];
    __shared__ unsigned sCnt[32];
    int tid = threadIdx.x;  // 1024
    int lane = tid & 31, wid = tid >> 5;
    float sum = 0.0f;
    unsigned cnt = 0u;
    for (int i = tid; i < N; i += 1024) {
        if (!g_low[i]) continue;
        unsigned ep = g_rowMinPos[i];
        if (ep == 0xFFFFFFFFu) continue;
        unsigned en = g_rowMaxNeg[i];
        if (en == 0u) continue;
        float minDot = decodeF(ep);
        float maxDot = decodeF(en);
        float hp = sqrtf(fmaxf(2.0f - 2.0f * minDot, 1e-12f));
        float hn = sqrtf(fmaxf(2.0f - 2.0f * maxDot, 1e-12f));
        float tl = hp - hn + 0.5f;
        if (tl < 0.0f) tl = 0.0f;
        sum += tl;
        cnt++;
    }
#pragma unroll
    for (int s = 16; s > 0; s >>= 1) {
        sum += __shfl_down_sync(0xffffffffu, sum, s);
        cnt += __shfl_down_sync(0xffffffffu, cnt, s);
    }
    if (lane == 0) { sSum[wid] = sum; sCnt[wid] = cnt; }
    __syncthreads();
    if (wid == 0) {
        float s2 = sSum[lane];
        unsigned c2 = sCnt[lane];
#pragma unroll
        for (int s = 16; s > 0; s >>= 1) {
            s2 += __shfl_down_sync(0xffffffffu, s2, s);
            c2 += __shfl_down_sync(0xffffffffu, c2, s);
        }
        if (lane == 0) out[0] = s2 / (float)(c2 > 0u ? c2 : 1u);
    }
    for (int i = tid; i < out_size; i += 1024)
        if (i > 0) out[i] = 0.0f;
}

// ---------------- launch ----------------
extern "C" void kernel_launch(void* const* d_in, const int* in_sizes, int n_in,
                              void* d_out, int out_size) {
    const float* emb = (const float*)d_in[0];
    const float* tg = (const float*)d_in[1];
    const float* au = (const float*)d_in[2];
    float* out = (float*)d_out;

    prepK<<<129, 1024>>>(emb, au);        // 1
    histP<1><<<512, 256>>>(tg);           // 2
    histP<2><<<512, 256>>>(tg);           // 3
    histP<3><<<512, 256>>>(tg);           // 4  (ncu captures this)
    histP<4><<<512, 256>>>(tg);           // 5
    gemmMaskK<<<528, 256>>>(tg);          // 6
    finalK<<<1, 1024>>>(out, out_size);   // 7
}

// round 9
// speedup vs baseline: 1.9986x; 1.0699x over previous
#include <cuda_runtime.h>
#include <cstdint>

#define N 4096
#define D 128
#define HBLK 256   // blocks per hist pass

// ---------------- device globals (scratch; no allocations allowed) ----------------
__device__ __align__(16) float g_en[N * D];   // normalized embeddings
__device__ unsigned char g_low[N];
__device__ unsigned g_rowMinPos[N];
__device__ unsigned g_rowMaxNeg[N];
__device__ unsigned g_hist1[4096];
__device__ unsigned g_hist2[4096];
__device__ unsigned g_hist3[256];
__device__ unsigned g_zeroPairs;
__device__ unsigned g_doneCtr[3];        // last-block counters for passes 1..3
__device__ unsigned g_p1, g_r1;          // pass1 selection
__device__ unsigned g_pfx24, g_r2;       // pass2 selection
__device__ unsigned g_mLo, g_mHi;
__device__ float    g_frac;
__device__ unsigned g_minAboveBin24;     // min b with (b>>8) > pfx24
__device__ float    g_actT;

// order-preserving float <-> uint encode
__device__ __forceinline__ unsigned encodeF(float f) {
    unsigned u = __float_as_uint(f);
    return (u & 0x80000000u) ? ~u : (u | 0x80000000u);
}
__device__ __forceinline__ float decodeF(unsigned u) {
    return (u & 0x80000000u) ? __uint_as_float(u & 0x7FFFFFFFu)
                             : __uint_as_float(~u);
}

// jax fp32-exact rank arithmetic
__device__ __forceinline__ void rankMath(unsigned z, unsigned& mLo, unsigned& mHi, float& frac) {
    unsigned long long n = 16773120ull - 2ull * (unsigned long long)z;
    float nf = (float)(n - 1ull);
    float pos = 0.2f * nf;
    float lof = floorf(pos);
    frac = pos - lof;
    unsigned fl = (unsigned)lof;
    mLo = fl >> 1;
    mHi = (fl + 1u) >> 1;
}

// ---- locate rank in a GLOBAL 4096-bin histogram; 256-thread block; __ldcg reads ----
__device__ void locateG4096(const unsigned* gh, unsigned rank,
                            volatile unsigned* wS,
                            volatile unsigned* outBin, volatile unsigned* outRem) {
    int tid = threadIdx.x, lane = tid & 31, wid = tid >> 5;
    unsigned hl[16];
    unsigned lsum = 0;
#pragma unroll
    for (int k = 0; k < 16; k++) { hl[k] = __ldcg(&gh[tid * 16 + k]); lsum += hl[k]; }
    unsigned v = lsum;
#pragma unroll
    for (int s = 1; s < 32; s <<= 1) {
        unsigned o = __shfl_up_sync(0xffffffffu, v, s);
        if (lane >= s) v += o;
    }
    if (lane == 31) wS[wid] = v;
    __syncthreads();
    if (tid == 0) { unsigned run = 0; for (int w = 0; w < 8; w++) { run += wS[w]; wS[w] = run; } }
    __syncthreads();
    unsigned cum = (v - lsum) + (wid ? wS[wid - 1] : 0u);
#pragma unroll
    for (int k = 0; k < 16; k++) {
        unsigned h = hl[k];
        if (h && rank >= cum && rank < cum + h) { *outBin = (unsigned)(tid * 16 + k); *outRem = rank - cum; }
        cum += h;
    }
    __syncthreads();
}

// ---- locate rank in GLOBAL 256-bin histogram (bin, rem, cnt); 256-thread block ----
__device__ void locateG256(const unsigned* gh, unsigned rank,
                           volatile unsigned* wS,
                           volatile unsigned* outBin, volatile unsigned* outRem,
                           volatile unsigned* outCnt) {
    int tid = threadIdx.x, lane = tid & 31, wid = tid >> 5;
    unsigned h = __ldcg(&gh[tid]);
    unsigned v = h;
#pragma unroll
    for (int s = 1; s < 32; s <<= 1) {
        unsigned o = __shfl_up_sync(0xffffffffu, v, s);
        if (lane >= s) v += o;
    }
    if (lane == 31) wS[wid] = v;
    __syncthreads();
    if (tid == 0) { unsigned run = 0; for (int w = 0; w < 8; w++) { run += wS[w]; wS[w] = run; } }
    __syncthreads();
    unsigned cum = (v - h) + (wid ? wS[wid - 1] : 0u);
    if (h && rank >= cum && rank < cum + h) { *outBin = (unsigned)tid; *outRem = rank - cum; *outCnt = h; }
    __syncthreads();
}

// ---- locate rank in SHARED 4096-bin hist; 1024-thread block (prep median) ----
__device__ void locateS4096_b1024(const unsigned* h, unsigned rank,
                                  volatile unsigned* wS,
                                  volatile unsigned* outBin, volatile unsigned* outRem) {
    int tid = threadIdx.x, lane = tid & 31, wid = tid >> 5;
    unsigned hl[4];
    unsigned lsum = 0;
#pragma unroll
    for (int k = 0; k < 4; k++) { hl[k] = h[tid * 4 + k]; lsum += hl[k]; }
    unsigned v = lsum;
#pragma unroll
    for (int s = 1; s < 32; s <<= 1) {
        unsigned o = __shfl_up_sync(0xffffffffu, v, s);
        if (lane >= s) v += o;
    }
    if (lane == 31) wS[wid] = v;
    __syncthreads();
    if (tid == 0) { unsigned run = 0; for (int w = 0; w < 32; w++) { run += wS[w]; wS[w] = run; } }
    __syncthreads();
    unsigned cum = (v - lsum) + (wid ? wS[wid - 1] : 0u);
#pragma unroll
    for (int k = 0; k < 4; k++) {
        unsigned hh = hl[k];
        if (hh && rank >= cum && rank < cum + hh) { *outBin = (unsigned)(tid * 4 + k); *outRem = rank - cum; }
        cum += hh;
    }
    __syncthreads();
}

// ---------------- K1: init + normalize + exact au-median (radix select) ----------------
__global__ void prepK(const float* __restrict__ emb, const float* __restrict__ au) {
    __shared__ unsigned e[4096];
    __shared__ unsigned h[4096];
    __shared__ unsigned wS[32];
    __shared__ unsigned sB, sR;
    int tid = threadIdx.x;  // 1024
    if (blockIdx.x < 128) {
        int row = blockIdx.x * 32 + (tid >> 5);
        int lane = tid & 31;
        const float4* p = (const float4*)(emb + (size_t)row * D);
        float4 v = p[lane];
        float ss = v.x * v.x + v.y * v.y + v.z * v.z + v.w * v.w;
#pragma unroll
        for (int st = 16; st > 0; st >>= 1) ss += __shfl_xor_sync(0xffffffffu, ss, st);
        float inv = 1.0f / fmaxf(sqrtf(ss), 1e-12f);
        float4 o;
        o.x = v.x * inv; o.y = v.y * inv; o.z = v.z * inv; o.w = v.w * inv;
        ((float4*)(g_en + (size_t)row * D))[lane] = o;
        return;
    }
    // block 128: init globals + median of au (ranks 2047, 2048)
    for (int x = tid; x < 4096; x += 1024) {
        g_rowMinPos[x] = 0xFFFFFFFFu;
        g_rowMaxNeg[x] = 0u;
        g_hist1[x] = 0u;
        g_hist2[x] = 0u;
    }
    for (int x = tid; x < 256; x += 1024) g_hist3[x] = 0u;
    if (tid < 3) g_doneCtr[tid] = 0u;
    if (tid == 0) { g_zeroPairs = 0u; g_minAboveBin24 = 0xFFFFFFFFu; }

    for (int i = tid; i < N; i += 1024) e[i] = encodeF(au[i]);
    __syncthreads();

    float vals[2];
#pragma unroll 1
    for (int r = 0; r < 2; r++) {
        unsigned rank = 2047u + (unsigned)r;
        for (int x = tid; x < 4096; x += 1024) h[x] = 0u;
        __syncthreads();
        for (int i = tid; i < N; i += 1024) atomicAdd(&h[e[i] >> 20], 1u);
        __syncthreads();
        locateS4096_b1024(h, rank, wS, &sB, &sR);
        unsigned b1 = sB, r1 = sR;
        __syncthreads();
        for (int x = tid; x < 4096; x += 1024) h[x] = 0u;
        __syncthreads();
        for (int i = tid; i < N; i += 1024)
            if ((e[i] >> 20) == b1) atomicAdd(&h[(e[i] >> 8) & 0xFFFu], 1u);
        __syncthreads();
        locateS4096_b1024(h, r1, wS, &sB, &sR);
        unsigned b2 = sB, r2 = sR;
        unsigned pfx = (b1 << 12) | b2;
        __syncthreads();
        for (int x = tid; x < 4096; x += 1024) h[x] = 0u;
        __syncthreads();
        for (int i = tid; i < N; i += 1024)
            if ((e[i] >> 8) == pfx) atomicAdd(&h[e[i] & 0xFFu], 1u);
        __syncthreads();
        locateS4096_b1024(h, r2, wS, &sB, &sR);
        unsigned b3 = sB;
        __syncthreads();
        vals[r] = decodeF((b1 << 20) | (b2 << 8) | b3);
    }
    float th = __fadd_rn(__fmul_rn(vals[0], 0.5f), __fmul_rn(vals[1], 0.5f));
    for (int i = tid; i < N; i += 1024) g_low[i] = (au[i] < th) ? 1 : 0;
}

// ---------------- hist passes over unordered pairs; selection done by LAST block ----------------
template <int PASS>
__global__ __launch_bounds__(256) void histP(const float* __restrict__ t) {
    __shared__ __align__(16) float4 tsv4[1024];
    __shared__ unsigned hist[4096];
    __shared__ unsigned wS[8];
    __shared__ unsigned sB, sR, sC, sNext;
    __shared__ unsigned sAgg;
    __shared__ int sLast;
    int tid = threadIdx.x;  // 256
    const float* tss = (const float*)tsv4;

    for (int k = tid; k < 1024; k += 256) tsv4[k] = ((const float4*)t)[k];
    if (PASS <= 2) { for (int x = tid; x < 4096; x += 256) hist[x] = 0u; }
    if (PASS == 3) { if (tid < 256) hist[tid] = 0u; }
    if (tid == 0) sAgg = (PASS == 3) ? 0xFFFFFFFFu : 0u;

    unsigned p1 = 0, pfx24 = 0;
    if (PASS == 2) p1 = __ldcg(&g_p1);
    if (PASS == 3) pfx24 = __ldcg(&g_pfx24);
    __syncthreads();

    // ---- main pair loop: rows strided by block, j vectorized float4 ----
    unsigned zc = 0u;
    unsigned myMin = 0xFFFFFFFFu;
    for (int i = blockIdx.x; i < N; i += HBLK) {
        float ti = tss[i];
        int v0 = (i + 1) >> 2;
        for (int v = v0 + tid; v < 1024; v += 256) {
            float4 w = tsv4[v];
            int jb = v << 2;
#pragma unroll
            for (int k = 0; k < 4; k++) {
                float tj = (k == 0) ? w.x : (k == 1) ? w.y : (k == 2) ? w.z : w.w;
                if (jb + k > i) {
                    unsigned b = __float_as_uint(fabsf(ti - tj));
                    if (PASS == 1) {
                        if (b == 0u) zc++;
                        else atomicAdd(&hist[b >> 20], 1u);
                    } else if (PASS == 2) {
                        if (b != 0u && (b >> 20) == p1) atomicAdd(&hist[(b >> 8) & 0xFFFu], 1u);
                    } else {
                        if (b != 0u) {
                            unsigned hi24 = b >> 8;
                            if (hi24 == pfx24) atomicAdd(&hist[b & 0xFFu], 1u);
                            else if (hi24 > pfx24) myMin = min(myMin, b);
                        }
                    }
                }
            }
        }
    }
    __syncthreads();

    // ---- flush ----
    if (PASS == 1) {
        for (int x = tid; x < 4096; x += 256)
            if (hist[x]) atomicAdd(&g_hist1[x], hist[x]);
#pragma unroll
        for (int s = 16; s > 0; s >>= 1) zc += __shfl_xor_sync(0xffffffffu, zc, s);
        if ((tid & 31) == 0 && zc) atomicAdd(&sAgg, zc);
        __syncthreads();
        if (tid == 0 && sAgg) atomicAdd(&g_zeroPairs, sAgg);
    } else if (PASS == 2) {
        for (int x = tid; x < 4096; x += 256)
            if (hist[x]) atomicAdd(&g_hist2[x], hist[x]);
    } else {
        if (tid < 256 && hist[tid]) atomicAdd(&g_hist3[tid], hist[tid]);
#pragma unroll
        for (int s = 16; s > 0; s >>= 1) myMin = min(myMin, __shfl_xor_sync(0xffffffffu, myMin, s));
        if ((tid & 31) == 0) atomicMin(&sAgg, myMin);
        __syncthreads();
        if (tid == 0 && sAgg != 0xFFFFFFFFu) atomicMin(&g_minAboveBin24, sAgg);
    }

    // ---- last-finishing block performs the selection for the next stage ----
    __threadfence();
    if (tid == 0) sLast = (atomicAdd(&g_doneCtr[PASS - 1], 1u) == (unsigned)(HBLK - 1)) ? 1 : 0;
    __syncthreads();
    if (!sLast) return;

    if (PASS == 1) {
        unsigned z = __ldcg(&g_zeroPairs);
        unsigned mLo, mHi; float frac;
        rankMath(z, mLo, mHi, frac);
        locateG4096(g_hist1, mLo, wS, &sB, &sR);
        if (tid == 0) {
            g_p1 = sB; g_r1 = sR;
            g_mLo = mLo; g_mHi = mHi; g_frac = frac;
        }
    } else if (PASS == 2) {
        unsigned r1 = __ldcg(&g_r1);
        locateG4096(g_hist2, r1, wS, &sB, &sR);
        if (tid == 0) { g_pfx24 = (p1 << 12) | sB; g_r2 = sR; }
    } else {
        unsigned r2 = __ldcg(&g_r2);
        locateG256(g_hist3, r2, wS, &sB, &sR, &sC);
        unsigned bin = sB, rem3 = sR, cnt3 = sC;
        if (tid == 0) sNext = 0xFFFFFFFFu;
        __syncthreads();
        // next nonzero hist3 bin above the selected one (same 24-bit prefix)
        if ((unsigned)tid > bin && __ldcg(&g_hist3[tid]) != 0u) atomicMin(&sNext, (unsigned)tid);
        __syncthreads();
        if (tid == 0) {
            unsigned vlo = (pfx24 << 8) | bin;
            unsigned mLo = __ldcg(&g_mLo), mHi = __ldcg(&g_mHi);
            float frac = __ldcg(&g_frac);
            bool same = (mHi == mLo) || (rem3 + 1u < cnt3);
            unsigned mAbove = __ldcg(&g_minAboveBin24);
            if (sNext != 0xFFFFFFFFu) mAbove = min(mAbove, (pfx24 << 8) | sNext);
            float flo = __uint_as_float(vlo);
            float fhi = same ? flo : __uint_as_float(mAbove);
            g_actT = __fadd_rn(__fmul_rn(flo, 1.0f - frac), __fmul_rn(fhi, frac));
        }
    }
}

// ---------------- K5: symmetric packed-f32x2 GEMM + fused masked row/col reductions ----------------
__global__ __launch_bounds__(256) void gemmMaskK(const float* __restrict__ t) {
    __shared__ __align__(16) float As[32][136];
    __shared__ __align__(16) float Bs[32][136];
    __shared__ unsigned sColMin[8][128];
    __shared__ unsigned sColMax[8][128];

    int tid = threadIdx.x;
    int b = blockIdx.x;
    int bi = 0;
    while (b >= 32 - bi) { b -= 32 - bi; bi++; }
    int bj = bi + b;
    int ri = bi * 128, rj = bj * 128;

    int r0 = (tid >> 4) * 4;
    int c0 = (tid & 15) * 4;

    // packed accumulators: [row][colpair], colpair covers (2c, 2c+1) within the 8-col frag
    unsigned long long acc2[8][4];
#pragma unroll
    for (int r = 0; r < 8; r++)
#pragma unroll
        for (int c = 0; c < 4; c++) acc2[r][c] = 0ull;

    int lr = tid >> 1, lh = tid & 1;
    for (int kc = 0; kc < 4; kc++) {
        const float4* pa = (const float4*)(g_en + (size_t)(ri + lr) * D + kc * 32 + lh * 16);
        const float4* pb = (const float4*)(g_en + (size_t)(rj + lr) * D + kc * 32 + lh * 16);
        float4 a0 = pa[0], a1 = pa[1], a2 = pa[2], a3 = pa[3];
        float4 b0 = pb[0], b1 = pb[1], b2 = pb[2], b3 = pb[3];
        if (kc) __syncthreads();
        int kb = lh * 16;
        As[kb + 0][lr] = a0.x; As[kb + 1][lr] = a0.y; As[kb + 2][lr] = a0.z; As[kb + 3][lr] = a0.w;
        As[kb + 4][lr] = a1.x; As[kb + 5][lr] = a1.y; As[kb + 6][lr] = a1.z; As[kb + 7][lr] = a1.w;
        As[kb + 8][lr] = a2.x; As[kb + 9][lr] = a2.y; As[kb + 10][lr] = a2.z; As[kb + 11][lr] = a2.w;
        As[kb + 12][lr] = a3.x; As[kb + 13][lr] = a3.y; As[kb + 14][lr] = a3.z; As[kb + 15][lr] = a3.w;
        Bs[kb + 0][lr] = b0.x; Bs[kb + 1][lr] = b0.y; Bs[kb + 2][lr] = b0.z; Bs[kb + 3][lr] = b0.w;
        Bs[kb + 4][lr] = b1.x; Bs[kb + 5][lr] = b1.y; Bs[kb + 6][lr] = b1.z; Bs[kb + 7][lr] = b1.w;
        Bs[kb + 8][lr] = b2.x; Bs[kb + 9][lr] = b2.y; Bs[kb + 10][lr] = b2.z; Bs[kb + 11][lr] = b2.w;
        Bs[kb + 12][lr] = b3.x; Bs[kb + 13][lr] = b3.y; Bs[kb + 14][lr] = b3.z; Bs[kb + 15][lr] = b3.w;
        __syncthreads();
#pragma unroll 8
        for (int k = 0; k < 32; k++) {
            float4 x0 = *(const float4*)&As[k][r0];
            float4 x1 = *(const float4*)&As[k][64 + r0];
            ulonglong2 B0 = *(const ulonglong2*)&Bs[k][c0];
            ulonglong2 B1 = *(const ulonglong2*)&Bs[k][64 + c0];
            float ar[8] = {x0.x, x0.y, x0.z, x0.w, x1.x, x1.y, x1.z, x1.w};
            unsigned long long bv[4] = {B0.x, B0.y, B1.x, B1.y};
#pragma unroll
            for (int r = 0; r < 8; r++) {
                unsigned long long av;
                asm("mov.b64 %0, {%1, %1};" : "=l"(av) : "r"(__float_as_uint(ar[r])));
#pragma unroll
                for (int c = 0; c < 4; c++)
                    asm("fma.rn.f32x2 %0, %1, %2, %0;"
                        : "+l"(acc2[r][c]) : "l"(av), "l"(bv[c]));
            }
        }
    }

    // unpack: dot[r][2c] = lo, dot[r][2c+1] = hi  (cols {c0..c0+3, 64+c0..64+c0+3})
    float dot[8][8];
#pragma unroll
    for (int r = 0; r < 8; r++)
#pragma unroll
        for (int c = 0; c < 4; c++) {
            dot[r][2 * c]     = __uint_as_float((unsigned)(acc2[r][c] & 0xFFFFFFFFull));
            dot[r][2 * c + 1] = __uint_as_float((unsigned)(acc2[r][c] >> 32));
        }

    float actT = __ldcg(&g_actT);

    int rows[8], cols[8];
#pragma unroll
    for (int u = 0; u < 4; u++) {
        rows[u] = ri + r0 + u;
        rows[4 + u] = ri + 64 + r0 + u;
        cols[u] = rj + c0 + u;
        cols[4 + u] = rj + 64 + c0 + u;
    }
    float ti[8], tj[8];
    int li[8], lj[8];
#pragma unroll
    for (int u = 0; u < 8; u++) {
        ti[u] = t[rows[u]];
        tj[u] = t[cols[u]];
        li[u] = g_low[rows[u]];
        lj[u] = g_low[cols[u]];
    }
    float pMin[8], nMax[8], cMin[8], cMax[8];
#pragma unroll
    for (int u = 0; u < 8; u++) {
        pMin[u] = 3.402823466e38f; nMax[u] = -3.402823466e38f;
        cMin[u] = 3.402823466e38f; cMax[u] = -3.402823466e38f;
    }
#pragma unroll
    for (int r = 0; r < 8; r++) {
#pragma unroll
        for (int c = 0; c < 8; c++) {
            float ad = fabsf(ti[r] - tj[c]);
            if (ad < actT) {
                float dv = dot[r][c];
                bool neq = rows[r] != cols[c];
                if (lj[c]) { if (neq) pMin[r] = fminf(pMin[r], dv); }
                else nMax[r] = fmaxf(nMax[r], dv);
                if (li[r]) { if (neq) cMin[c] = fminf(cMin[c], dv); }
                else cMax[c] = fmaxf(cMax[c], dv);
            }
        }
    }
#pragma unroll
    for (int s = 8; s > 0; s >>= 1) {
#pragma unroll
        for (int r = 0; r < 8; r++) {
            pMin[r] = fminf(pMin[r], __shfl_down_sync(0xffffffffu, pMin[r], s, 16));
            nMax[r] = fmaxf(nMax[r], __shfl_down_sync(0xffffffffu, nMax[r], s, 16));
        }
    }
    if ((tid & 15) == 0) {
#pragma unroll
        for (int r = 0; r < 8; r++) {
            if (pMin[r] < 3.0e38f) atomicMin(&g_rowMinPos[rows[r]], encodeF(pMin[r]));
            if (nMax[r] > -3.0e38f) atomicMax(&g_rowMaxNeg[rows[r]], encodeF(nMax[r]));
        }
    }
    unsigned eMin[8], eMax[8];
#pragma unroll
    for (int u = 0; u < 8; u++) {
        eMin[u] = encodeF(cMin[u]);
        eMax[u] = encodeF(cMax[u]);
        eMin[u] = min(eMin[u], __shfl_xor_sync(0xffffffffu, eMin[u], 16));
        eMax[u] = max(eMax[u], __shfl_xor_sync(0xffffffffu, eMax[u], 16));
    }
    int wrp = tid >> 5;
    if ((tid & 31) < 16) {
#pragma unroll
        for (int u = 0; u < 4; u++) {
            sColMin[wrp][c0 + u] = eMin[u];
            sColMin[wrp][64 + c0 + u] = eMin[4 + u];
            sColMax[wrp][c0 + u] = eMax[u];
            sColMax[wrp][64 + c0 + u] = eMax[4 + u];
        }
    }
    __syncthreads();
    if (tid < 128) {
        unsigned v = sColMin[0][tid];
#pragma unroll
        for (int w = 1; w < 8; w++) v = min(v, sColMin[w][tid]);
        if (v < 0xFF000000u) atomicMin(&g_rowMinPos[rj + tid], v);
    } else if (tid < 256) {
        int c = tid - 128;
        unsigned v = sColMax[0][c];
#pragma unroll
        for (int w = 1; w < 8; w++) v = max(v, sColMax[w][c]);
        if (v > 0x01000000u) atomicMax(&g_rowMaxNeg[rj + c], v);
    }
}

// ---------------- K6: per-anchor loss + mean ----------------
__global__ void finalK(float* __restrict__ out, int out_size) {
    __shared__ float sSum[32];
    __shared__ unsigned sCnt[32];
    int tid = threadIdx.x;  // 1024
    int lane = tid & 31, wid = tid >> 5;
    float sum = 0.0f;
    unsigned cnt = 0u;
    for (int i = tid; i < N; i += 1024) {
        if (!g_low[i]) continue;
        unsigned ep = g_rowMinPos[i];
        if (ep == 0xFFFFFFFFu) continue;
        unsigned en = g_rowMaxNeg[i];
        if (en == 0u) continue;
        float minDot = decodeF(ep);
        float maxDot = decodeF(en);
        float hp = sqrtf(fmaxf(2.0f - 2.0f * minDot, 1e-12f));
        float hn = sqrtf(fmaxf(2.0f - 2.0f * maxDot, 1e-12f));
        float tl = hp - hn + 0.5f;
        if (tl < 0.0f) tl = 0.0f;
        sum += tl;
        cnt++;
    }
#pragma unroll
    for (int s = 16; s > 0; s >>= 1) {
        sum += __shfl_down_sync(0xffffffffu, sum, s);
        cnt += __shfl_down_sync(0xffffffffu, cnt, s);
    }
    if (lane == 0) { sSum[wid] = sum; sCnt[wid] = cnt; }
    __syncthreads();
    if (wid == 0) {
        float s2 = sSum[lane];
        unsigned c2 = sCnt[lane];
#pragma unroll
        for (int s = 16; s > 0; s >>= 1) {
            s2 += __shfl_down_sync(0xffffffffu, s2, s);
            c2 += __shfl_down_sync(0xffffffffu, c2, s);
        }
        if (lane == 0) out[0] = s2 / (float)(c2 > 0u ? c2 : 1u);
    }
    for (int i = tid; i < out_size; i += 1024)
        if (i > 0) out[i] = 0.0f;
}

// ---------------- launch ----------------
extern "C" void kernel_launch(void* const* d_in, const int* in_sizes, int n_in,
                              void* d_out, int out_size) {
    const float* emb = (const float*)d_in[0];
    const float* tg = (const float*)d_in[1];
    const float* au = (const float*)d_in[2];
    float* out = (float*)d_out;

    prepK<<<129, 1024>>>(emb, au);        // 1
    histP<1><<<HBLK, 256>>>(tg);          // 2
    histP<2><<<HBLK, 256>>>(tg);          // 3
    histP<3><<<HBLK, 256>>>(tg);          // 4  (ncu captures this)
    gemmMaskK<<<528, 256>>>(tg);          // 5
    finalK<<<1, 1024>>>(out, out_size);   // 6
}

// round 10
// speedup vs baseline: 2.0583x; 1.0299x over previous
#include <cuda_runtime.h>
#include <cstdint>

#define N 4096
#define D 128
#define HB1 256   // pass1 blocks
#define HB2 256   // pass2 blocks
#define GB  528   // gemm blocks

// ---------------- device globals (all accumulators have identity == 0) ----------------
__device__ __align__(16) float g_en[N * D];
__device__ unsigned char g_low[N];
__device__ unsigned g_rowMinInv[N];      // ~encodeF(min pos-dot), atomicMax, 0 = empty
__device__ unsigned g_rowMaxNeg[N];      // encodeF(max neg-dot), atomicMax, 0 = empty
__device__ unsigned g_hist1[4096];
__device__ unsigned g_hist2[4096];
__device__ unsigned g_hist20[1 << 20];   // exact-value hist within p1 prefix (bits 19:0)
__device__ unsigned g_zeroPairs;
__device__ unsigned g_doneCtr[4];
__device__ unsigned g_p1, g_r1, g_mLo, g_mHi;
__device__ float    g_frac;
__device__ unsigned g_minCrossInv;       // ~min b with top12 > p1, atomicMax, 0 = empty
__device__ unsigned g_actReady;          // float bits of actT; 0 = not ready

__device__ __forceinline__ unsigned encodeF(float f) {
    unsigned u = __float_as_uint(f);
    return (u & 0x80000000u) ? ~u : (u | 0x80000000u);
}
__device__ __forceinline__ float decodeF(unsigned u) {
    return (u & 0x80000000u) ? __uint_as_float(u & 0x7FFFFFFFu)
                             : __uint_as_float(~u);
}

__device__ __forceinline__ void rankMath(unsigned z, unsigned& mLo, unsigned& mHi, float& frac) {
    unsigned long long n = 16773120ull - 2ull * (unsigned long long)z;
    float nf = (float)(n - 1ull);
    float pos = 0.2f * nf;
    float lof = floorf(pos);
    frac = pos - lof;
    unsigned fl = (unsigned)lof;
    mLo = fl >> 1;
    mHi = (fl + 1u) >> 1;
}

// ---- locate rank in a GLOBAL 4096-bin histogram; 256-thread block; __ldcg ----
__device__ void locateG4096(const unsigned* gh, unsigned rank,
                            volatile unsigned* wS,
                            volatile unsigned* outBin, volatile unsigned* outRem) {
    int tid = threadIdx.x, lane = tid & 31, wid = tid >> 5;
    unsigned hl[16];
    unsigned lsum = 0;
#pragma unroll
    for (int k = 0; k < 16; k++) { hl[k] = __ldcg(&gh[tid * 16 + k]); lsum += hl[k]; }
    unsigned v = lsum;
#pragma unroll
    for (int s = 1; s < 32; s <<= 1) {
        unsigned o = __shfl_up_sync(0xffffffffu, v, s);
        if (lane >= s) v += o;
    }
    if (lane == 31) wS[wid] = v;
    __syncthreads();
    if (tid == 0) { unsigned run = 0; for (int w = 0; w < 8; w++) { run += wS[w]; wS[w] = run; } }
    __syncthreads();
    unsigned cum = (v - lsum) + (wid ? wS[wid - 1] : 0u);
#pragma unroll
    for (int k = 0; k < 16; k++) {
        unsigned h = hl[k];
        if (h && rank >= cum && rank < cum + h) { *outBin = (unsigned)(tid * 16 + k); *outRem = rank - cum; }
        cum += h;
    }
    __syncthreads();
}

// ---- locate rank in GLOBAL 256-entry table (bin, rem, cnt); 256-thread block ----
__device__ void locateG256(const unsigned* gh, unsigned rank,
                           volatile unsigned* wS,
                           volatile unsigned* outBin, volatile unsigned* outRem,
                           volatile unsigned* outCnt) {
    int tid = threadIdx.x, lane = tid & 31, wid = tid >> 5;
    unsigned h = __ldcg(&gh[tid]);
    unsigned v = h;
#pragma unroll
    for (int s = 1; s < 32; s <<= 1) {
        unsigned o = __shfl_up_sync(0xffffffffu, v, s);
        if (lane >= s) v += o;
    }
    if (lane == 31) wS[wid] = v;
    __syncthreads();
    if (tid == 0) { unsigned run = 0; for (int w = 0; w < 8; w++) { run += wS[w]; wS[w] = run; } }
    __syncthreads();
    unsigned cum = (v - h) + (wid ? wS[wid - 1] : 0u);
    if (h && rank >= cum && rank < cum + h) { *outBin = (unsigned)tid; *outRem = rank - cum; *outCnt = h; }
    __syncthreads();
}

// ---- locate rank in SHARED 4096-bin histogram; 256-thread block; plain loads ----
__device__ void locateS4096(const unsigned* h, unsigned rank,
                            volatile unsigned* wS,
                            volatile unsigned* outBin, volatile unsigned* outRem) {
    int tid = threadIdx.x, lane = tid & 31, wid = tid >> 5;
    unsigned hl[16];
    unsigned lsum = 0;
#pragma unroll
    for (int k = 0; k < 16; k++) { hl[k] = h[tid * 16 + k]; lsum += hl[k]; }
    unsigned v = lsum;
#pragma unroll
    for (int s = 1; s < 32; s <<= 1) {
        unsigned o = __shfl_up_sync(0xffffffffu, v, s);
        if (lane >= s) v += o;
    }
    if (lane == 31) wS[wid] = v;
    __syncthreads();
    if (tid == 0) { unsigned run = 0; for (int w = 0; w < 8; w++) { run += wS[w]; wS[w] = run; } }
    __syncthreads();
    unsigned cum = (v - lsum) + (wid ? wS[wid - 1] : 0u);
#pragma unroll
    for (int k = 0; k < 16; k++) {
        unsigned hh = hl[k];
        if (hh && rank >= cum && rank < cum + hh) { *outBin = (unsigned)(tid * 16 + k); *outRem = rank - cum; }
        cum += hh;
    }
    __syncthreads();
}

// ================ K1: [pass1: bids 0-255] + [normalize+zero20: 256-383] + [median: 384] ================
__global__ __launch_bounds__(256) void prepPass1K(const float* __restrict__ t,
                                                  const float* __restrict__ emb,
                                                  const float* __restrict__ au) {
    __shared__ __align__(16) unsigned char sbuf[32768];
    __shared__ unsigned wS[8];
    __shared__ unsigned sA, sB_;
    __shared__ unsigned sAgg;
    __shared__ int sLast;
    int tid = threadIdx.x;
    int bid = blockIdx.x;

    if (bid < HB1) {
        // ---------------- pass 1: 12-bit smem histogram + tie count ----------------
        float4* tsv4 = (float4*)sbuf;
        unsigned* hist = (unsigned*)(sbuf + 16384);
        const float* tss = (const float*)tsv4;
        for (int k = tid; k < 1024; k += 256) tsv4[k] = ((const float4*)t)[k];
        for (int x = tid; x < 4096; x += 256) hist[x] = 0u;
        if (tid == 0) sAgg = 0u;
        __syncthreads();

        unsigned zc = 0u;
        for (int i = bid; i < N; i += HB1) {
            float ti = tss[i];
            int v0 = (i + 1) >> 2;
            for (int v = v0 + tid; v < 1024; v += 256) {
                float4 w = tsv4[v];
                int jb = v << 2;
#pragma unroll
                for (int k = 0; k < 4; k++) {
                    float tj = (k == 0) ? w.x : (k == 1) ? w.y : (k == 2) ? w.z : w.w;
                    if (jb + k > i) {
                        unsigned b = __float_as_uint(fabsf(ti - tj));
                        if (b == 0u) zc++;
                        else atomicAdd(&hist[b >> 20], 1u);
                    }
                }
            }
        }
        __syncthreads();
        for (int x = tid; x < 4096; x += 256)
            if (hist[x]) atomicAdd(&g_hist1[x], hist[x]);
#pragma unroll
        for (int s = 16; s > 0; s >>= 1) zc += __shfl_xor_sync(0xffffffffu, zc, s);
        if ((tid & 31) == 0 && zc) atomicAdd(&sAgg, zc);
        __syncthreads();
        if (tid == 0 && sAgg) atomicAdd(&g_zeroPairs, sAgg);

        __threadfence();
        if (tid == 0) sLast = (atomicAdd(&g_doneCtr[0], 1u) == (unsigned)(HB1 - 1)) ? 1 : 0;
        __syncthreads();
        if (!sLast) return;

        unsigned z = __ldcg(&g_zeroPairs);
        unsigned mLo, mHi; float frac;
        rankMath(z, mLo, mHi, frac);
        locateG4096(g_hist1, mLo, wS, &sA, &sB_);
        if (tid == 0) {
            g_p1 = sA; g_r1 = sB_;
            g_mLo = mLo; g_mHi = mHi; g_frac = frac;
        }
        return;
    }

    if (bid < HB1 + 128) {
        // ---------------- normalize 32 rows + zero hist20 slice ----------------
        int nb = bid - HB1;
        for (int x = tid; x < 8192; x += 256) g_hist20[nb * 8192 + x] = 0u;
        int warp = tid >> 5, lane = tid & 31;
#pragma unroll
        for (int q = 0; q < 4; q++) {
            int row = nb * 32 + warp * 4 + q;
            const float4* p = (const float4*)(emb + (size_t)row * D);
            float4 v = p[lane];
            float ss = v.x * v.x + v.y * v.y + v.z * v.z + v.w * v.w;
#pragma unroll
            for (int st = 16; st > 0; st >>= 1) ss += __shfl_xor_sync(0xffffffffu, ss, st);
            float inv = 1.0f / fmaxf(sqrtf(ss), 1e-12f);
            float4 o;
            o.x = v.x * inv; o.y = v.y * inv; o.z = v.z * inv; o.w = v.w * inv;
            ((float4*)(g_en + (size_t)row * D))[lane] = o;
        }
        return;
    }

    // ---------------- median of au via 3-level radix select (ranks 2047, 2048) ----------------
    {
        unsigned* e = (unsigned*)sbuf;             // 4096
        unsigned* h = (unsigned*)(sbuf + 16384);   // 4096
        for (int i = tid; i < N; i += 256) e[i] = encodeF(au[i]);
        __syncthreads();
        float vals[2];
#pragma unroll 1
        for (int r = 0; r < 2; r++) {
            unsigned rank = 2047u + (unsigned)r;
            for (int x = tid; x < 4096; x += 256) h[x] = 0u;
            __syncthreads();
            for (int i = tid; i < N; i += 256) atomicAdd(&h[e[i] >> 20], 1u);
            __syncthreads();
            locateS4096(h, rank, wS, &sA, &sB_);
            unsigned b1 = sA, r1 = sB_;
            __syncthreads();
            for (int x = tid; x < 4096; x += 256) h[x] = 0u;
            __syncthreads();
            for (int i = tid; i < N; i += 256)
                if ((e[i] >> 20) == b1) atomicAdd(&h[(e[i] >> 8) & 0xFFFu], 1u);
            __syncthreads();
            locateS4096(h, r1, wS, &sA, &sB_);
            unsigned b2 = sA, r2 = sB_;
            unsigned pfx = (b1 << 12) | b2;
            __syncthreads();
            for (int x = tid; x < 4096; x += 256) h[x] = 0u;
            __syncthreads();
            for (int i = tid; i < N; i += 256)
                if ((e[i] >> 8) == pfx) atomicAdd(&h[e[i] & 0xFFu], 1u);
            __syncthreads();
            locateS4096(h, r2, wS, &sA, &sB_);
            unsigned b3 = sA;
            __syncthreads();
            vals[r] = decodeF((b1 << 20) | (b2 << 8) | b3);
        }
        float th = __fadd_rn(__fmul_rn(vals[0], 0.5f), __fmul_rn(vals[1], 0.5f));
        for (int i = tid; i < N; i += 256) g_low[i] = (au[i] < th) ? 1 : 0;
    }
}

// ================ K2: [pass2: bids 0-255] + [gemm: 256-783, spins for actT; last does final+resets] ================
__global__ __launch_bounds__(256) void pass2GemmK(const float* __restrict__ t,
                                                  float* __restrict__ out, int out_size) {
    __shared__ __align__(16) unsigned char sbuf[43520];
    __shared__ unsigned wS[8];
    __shared__ unsigned sA, sB_, sC_, sD_;
    __shared__ unsigned sAgg;
    __shared__ int sLast;
    int tid = threadIdx.x;

    if (blockIdx.x < HB2) {
        // ---------------- pass 2: hist2 (bits 19:8 in p1) + exact hist20 + cross-min ----------------
        float4* tsv4 = (float4*)sbuf;
        unsigned* sh2 = (unsigned*)(sbuf + 16384);
        const float* tss = (const float*)tsv4;
        for (int k = tid; k < 1024; k += 256) tsv4[k] = ((const float4*)t)[k];
        for (int x = tid; x < 4096; x += 256) sh2[x] = 0u;
        if (tid == 0) sAgg = 0u;
        unsigned p1 = g_p1;   // written in K1 (previous launch)
        __syncthreads();

        unsigned myInv = 0u;
        for (int i = blockIdx.x; i < N; i += HB2) {
            float ti = tss[i];
            int v0 = (i + 1) >> 2;
            for (int v = v0 + tid; v < 1024; v += 256) {
                float4 w = tsv4[v];
                int jb = v << 2;
#pragma unroll
                for (int k = 0; k < 4; k++) {
                    float tj = (k == 0) ? w.x : (k == 1) ? w.y : (k == 2) ? w.z : w.w;
                    if (jb + k > i) {
                        unsigned b = __float_as_uint(fabsf(ti - tj));
                        if (b != 0u) {
                            unsigned t12 = b >> 20;
                            if (t12 == p1) {
                                atomicAdd(&sh2[(b >> 8) & 0xFFFu], 1u);
                                atomicAdd(&g_hist20[b & 0xFFFFFu], 1u);
                            } else if (t12 > p1) {
                                myInv = max(myInv, ~b);
                            }
                        }
                    }
                }
            }
        }
        __syncthreads();
        for (int x = tid; x < 4096; x += 256)
            if (sh2[x]) atomicAdd(&g_hist2[x], sh2[x]);
#pragma unroll
        for (int s = 16; s > 0; s >>= 1) myInv = max(myInv, __shfl_xor_sync(0xffffffffu, myInv, s));
        if ((tid & 31) == 0 && myInv) atomicMax(&sAgg, myInv);
        __syncthreads();
        if (tid == 0 && sAgg) atomicMax(&g_minCrossInv, sAgg);

        __threadfence();
        if (tid == 0) sLast = (atomicAdd(&g_doneCtr[1], 1u) == (unsigned)(HB2 - 1)) ? 1 : 0;
        __syncthreads();
        if (!sLast) return;

        // ---- selection: exact vlo, multiplicity, next distinct value ----
        unsigned r1 = g_r1;
        locateG4096(g_hist2, r1, wS, &sA, &sB_);
        unsigned bin2 = sA, rem2 = sB_;
        __syncthreads();
        locateG256(&g_hist20[bin2 << 8], rem2, wS, &sA, &sB_, &sC_);
        unsigned bin3 = sA, rem3 = sB_, cnt3 = sC_;
        __syncthreads();
        if (tid == 0) { sA = 0xFFFFFFFFu; sB_ = 0xFFFFFFFFu; sD_ = 0xFFFFFFFFu; }
        __syncthreads();
        // (a) next nonzero exact-value above bin3 within the segment
        if ((unsigned)tid > bin3 && __ldcg(&g_hist20[(bin2 << 8) + tid]) != 0u)
            atomicMin(&sA, (unsigned)tid);
        // (b) next nonzero hist2 bin above bin2
#pragma unroll
        for (int k = 0; k < 16; k++) {
            unsigned idx = (unsigned)tid * 16u + (unsigned)k;
            if (idx > bin2 && __ldcg(&g_hist2[idx]) != 0u) atomicMin(&sB_, idx);
        }
        __syncthreads();
        unsigned nextA = sA, nbin2 = sB_;
        if (nbin2 != 0xFFFFFFFFu) {
            if (__ldcg(&g_hist20[(nbin2 << 8) + tid]) != 0u) atomicMin(&sD_, (unsigned)tid);
        }
        __syncthreads();
        if (tid == 0) {
            unsigned vlo = (p1 << 20) | (bin2 << 8) | bin3;
            unsigned mLo = g_mLo, mHi = g_mHi;
            float frac = g_frac;
            unsigned mAb = 0xFFFFFFFFu;
            if (nextA != 0xFFFFFFFFu) mAb = min(mAb, (p1 << 20) | (bin2 << 8) | nextA);
            if (nbin2 != 0xFFFFFFFFu && sD_ != 0xFFFFFFFFu)
                mAb = min(mAb, (p1 << 20) | (nbin2 << 8) | sD_);
            unsigned crossInv = __ldcg(&g_minCrossInv);
            if (crossInv) mAb = min(mAb, ~crossInv);
            bool same = (mHi == mLo) || (rem3 + 1u < cnt3);
            float flo = __uint_as_float(vlo);
            float fhi = same ? flo : __uint_as_float(mAb);
            float actT = __fadd_rn(__fmul_rn(flo, 1.0f - frac), __fmul_rn(fhi, frac));
            __threadfence();
            atomicExch(&g_actReady, __float_as_uint(actT));
        }
        return;
    }

    // ---------------- gemm tiles ----------------
    float (*As)[136] = (float (*)[136])sbuf;
    float (*Bs)[136] = (float (*)[136])(sbuf + 17408);
    unsigned* sColMin = (unsigned*)(sbuf + 34816);   // [8][128]
    unsigned* sColMax = (unsigned*)(sbuf + 38912);   // [8][128]

    int b = blockIdx.x - HB2;
    int bi = 0;
    while (b >= 32 - bi) { b -= 32 - bi; bi++; }
    int bj = bi + b;
    int ri = bi * 128, rj = bj * 128;

    int r0 = (tid >> 4) * 4;
    int c0 = (tid & 15) * 4;

    unsigned long long acc2[8][4];
#pragma unroll
    for (int r = 0; r < 8; r++)
#pragma unroll
        for (int c = 0; c < 4; c++) acc2[r][c] = 0ull;

    int lr = tid >> 1, lh = tid & 1;
    for (int kc = 0; kc < 4; kc++) {
        const float4* pa = (const float4*)(g_en + (size_t)(ri + lr) * D + kc * 32 + lh * 16);
        const float4* pb = (const float4*)(g_en + (size_t)(rj + lr) * D + kc * 32 + lh * 16);
        float4 a0 = pa[0], a1 = pa[1], a2 = pa[2], a3 = pa[3];
        float4 b0 = pb[0], b1 = pb[1], b2 = pb[2], b3 = pb[3];
        if (kc) __syncthreads();
        int kb = lh * 16;
        As[kb + 0][lr] = a0.x; As[kb + 1][lr] = a0.y; As[kb + 2][lr] = a0.z; As[kb + 3][lr] = a0.w;
        As[kb + 4][lr] = a1.x; As[kb + 5][lr] = a1.y; As[kb + 6][lr] = a1.z; As[kb + 7][lr] = a1.w;
        As[kb + 8][lr] = a2.x; As[kb + 9][lr] = a2.y; As[kb + 10][lr] = a2.z; As[kb + 11][lr] = a2.w;
        As[kb + 12][lr] = a3.x; As[kb + 13][lr] = a3.y; As[kb + 14][lr] = a3.z; As[kb + 15][lr] = a3.w;
        Bs[kb + 0][lr] = b0.x; Bs[kb + 1][lr] = b0.y; Bs[kb + 2][lr] = b0.z; Bs[kb + 3][lr] = b0.w;
        Bs[kb + 4][lr] = b1.x; Bs[kb + 5][lr] = b1.y; Bs[kb + 6][lr] = b1.z; Bs[kb + 7][lr] = b1.w;
        Bs[kb + 8][lr] = b2.x; Bs[kb + 9][lr] = b2.y; Bs[kb + 10][lr] = b2.z; Bs[kb + 11][lr] = b2.w;
        Bs[kb + 12][lr] = b3.x; Bs[kb + 13][lr] = b3.y; Bs[kb + 14][lr] = b3.z; Bs[kb + 15][lr] = b3.w;
        __syncthreads();
#pragma unroll 8
        for (int k = 0; k < 32; k++) {
            float4 x0 = *(const float4*)&As[k][r0];
            float4 x1 = *(const float4*)&As[k][64 + r0];
            ulonglong2 B0 = *(const ulonglong2*)&Bs[k][c0];
            ulonglong2 B1 = *(const ulonglong2*)&Bs[k][64 + c0];
            float ar[8] = {x0.x, x0.y, x0.z, x0.w, x1.x, x1.y, x1.z, x1.w};
            unsigned long long bv[4] = {B0.x, B0.y, B1.x, B1.y};
#pragma unroll
            for (int r = 0; r < 8; r++) {
                unsigned long long av;
                asm("mov.b64 %0, {%1, %1};" : "=l"(av) : "r"(__float_as_uint(ar[r])));
#pragma unroll
                for (int c = 0; c < 4; c++)
                    asm("fma.rn.f32x2 %0, %1, %2, %0;"
                        : "+l"(acc2[r][c]) : "l"(av), "l"(bv[c]));
            }
        }
    }

    float dot[8][8];
#pragma unroll
    for (int r = 0; r < 8; r++)
#pragma unroll
        for (int c = 0; c < 4; c++) {
            dot[r][2 * c]     = __uint_as_float((unsigned)(acc2[r][c] & 0xFFFFFFFFull));
            dot[r][2 * c + 1] = __uint_as_float((unsigned)(acc2[r][c] >> 32));
        }

    // wait for pass2's threshold (usually ready long before the mainloop ends)
    unsigned ab;
    do {
        ab = *(volatile unsigned*)&g_actReady;
        if (ab == 0u) __nanosleep(64);
    } while (ab == 0u);
    float actT = __uint_as_float(ab);

    int rows[8], cols[8];
#pragma unroll
    for (int u = 0; u < 4; u++) {
        rows[u] = ri + r0 + u;
        rows[4 + u] = ri + 64 + r0 + u;
        cols[u] = rj + c0 + u;
        cols[4 + u] = rj + 64 + c0 + u;
    }
    float ti[8], tj[8];
    int li[8], lj[8];
#pragma unroll
    for (int u = 0; u < 8; u++) {
        ti[u] = t[rows[u]];
        tj[u] = t[cols[u]];
        li[u] = g_low[rows[u]];
        lj[u] = g_low[cols[u]];
    }
    float pMin[8], nMax[8], cMin[8], cMax[8];
#pragma unroll
    for (int u = 0; u < 8; u++) {
        pMin[u] = 3.402823466e38f; nMax[u] = -3.402823466e38f;
        cMin[u] = 3.402823466e38f; cMax[u] = -3.402823466e38f;
    }
#pragma unroll
    for (int r = 0; r < 8; r++) {
#pragma unroll
        for (int c = 0; c < 8; c++) {
            float ad = fabsf(ti[r] - tj[c]);
            if (ad < actT) {
                float dv = dot[r][c];
                bool neq = rows[r] != cols[c];
                if (lj[c]) { if (neq) pMin[r] = fminf(pMin[r], dv); }
                else nMax[r] = fmaxf(nMax[r], dv);
                if (li[r]) { if (neq) cMin[c] = fminf(cMin[c], dv); }
                else cMax[c] = fmaxf(cMax[c], dv);
            }
        }
    }
#pragma unroll
    for (int s = 8; s > 0; s >>= 1) {
#pragma unroll
        for (int r = 0; r < 8; r++) {
            pMin[r] = fminf(pMin[r], __shfl_down_sync(0xffffffffu, pMin[r], s, 16));
            nMax[r] = fmaxf(nMax[r], __shfl_down_sync(0xffffffffu, nMax[r], s, 16));
        }
    }
    if ((tid & 15) == 0) {
#pragma unroll
        for (int r = 0; r < 8; r++) {
            if (pMin[r] < 3.0e38f) atomicMax(&g_rowMinInv[rows[r]], ~encodeF(pMin[r]));
            if (nMax[r] > -3.0e38f) atomicMax(&g_rowMaxNeg[rows[r]], encodeF(nMax[r]));
        }
    }
    unsigned eMinI[8], eMax[8];
#pragma unroll
    for (int u = 0; u < 8; u++) {
        eMinI[u] = ~encodeF(cMin[u]);
        eMax[u] = encodeF(cMax[u]);
        eMinI[u] = max(eMinI[u], __shfl_xor_sync(0xffffffffu, eMinI[u], 16));
        eMax[u] = max(eMax[u], __shfl_xor_sync(0xffffffffu, eMax[u], 16));
    }
    int wrp = tid >> 5;
    __syncthreads();
    if ((tid & 31) < 16) {
#pragma unroll
        for (int u = 0; u < 4; u++) {
            sColMin[wrp * 128 + c0 + u] = eMinI[u];
            sColMin[wrp * 128 + 64 + c0 + u] = eMinI[4 + u];
            sColMax[wrp * 128 + c0 + u] = eMax[u];
            sColMax[wrp * 128 + 64 + c0 + u] = eMax[4 + u];
        }
    }
    __syncthreads();
    if (tid < 128) {
        unsigned v = sColMin[tid];
#pragma unroll
        for (int w = 1; w < 8; w++) v = max(v, sColMin[w * 128 + tid]);
        if (v > 0x00800000u) atomicMax(&g_rowMinInv[rj + tid], v);
    } else {
        int c = tid - 128;
        unsigned v = sColMax[c];
#pragma unroll
        for (int w = 1; w < 8; w++) v = max(v, sColMax[w * 128 + c]);
        if (v > 0x01000000u) atomicMax(&g_rowMaxNeg[rj + c], v);
    }

    // ---- last gemm block: final loss + reset all accumulators ----
    __threadfence();
    if (tid == 0) sLast = (atomicAdd(&g_doneCtr[2], 1u) == (unsigned)(GB - 1)) ? 1 : 0;
    __syncthreads();
    if (!sLast) return;

    float sum = 0.0f;
    unsigned cnt = 0u;
    for (int i = tid; i < N; i += 256) {
        if (g_low[i] == 0) continue;
        unsigned rInv = __ldcg(&g_rowMinInv[i]);
        if (rInv == 0u) continue;
        unsigned en = __ldcg(&g_rowMaxNeg[i]);
        if (en == 0u) continue;
        float minDot = decodeF(~rInv);
        float maxDot = decodeF(en);
        float hp = sqrtf(fmaxf(2.0f - 2.0f * minDot, 1e-12f));
        float hn = sqrtf(fmaxf(2.0f - 2.0f * maxDot, 1e-12f));
        float tl = hp - hn + 0.5f;
        if (tl < 0.0f) tl = 0.0f;
        sum += tl;
        cnt++;
    }
    int lane = tid & 31;
#pragma unroll
    for (int s = 16; s > 0; s >>= 1) {
        sum += __shfl_down_sync(0xffffffffu, sum, s);
        cnt += __shfl_down_sync(0xffffffffu, cnt, s);
    }
    __syncthreads();
    float* fred = (float*)sbuf;
    unsigned* ured = (unsigned*)(sbuf + 64);
    if (lane == 0) { fred[wrp] = sum; ured[wrp] = cnt; }
    __syncthreads();
    if (wrp == 0) {
        float s2 = (lane < 8) ? fred[lane] : 0.0f;
        unsigned c2 = (lane < 8) ? ured[lane] : 0u;
#pragma unroll
        for (int s = 4; s > 0; s >>= 1) {
            s2 += __shfl_down_sync(0xffffffffu, s2, s);
            c2 += __shfl_down_sync(0xffffffffu, c2, s);
        }
        if (lane == 0) out[0] = s2 / (float)(c2 > 0u ? c2 : 1u);
    }
    for (int i = tid; i < out_size; i += 256)
        if (i > 0) out[i] = 0.0f;

    // resets (identity 0 everywhere); g_hist20 is re-zeroed by next K1
    for (int x = tid; x < 4096; x += 256) {
        g_hist1[x] = 0u;
        g_hist2[x] = 0u;
        g_rowMinInv[x] = 0u;
        g_rowMaxNeg[x] = 0u;
    }
    if (tid < 4) g_doneCtr[tid] = 0u;
    if (tid == 0) {
        g_zeroPairs = 0u;
        g_minCrossInv = 0u;
        g_actReady = 0u;
    }
}

// ---------------- launch ----------------
extern "C" void kernel_launch(void* const* d_in, const int* in_sizes, int n_in,
                              void* d_out, int out_size) {
    const float* emb = (const float*)d_in[0];
    const float* tg = (const float*)d_in[1];
    const float* au = (const float*)d_in[2];
    float* out = (float*)d_out;

    prepPass1K<<<HB1 + 128 + 1, 256>>>(tg, emb, au);   // 1
    pass2GemmK<<<HB2 + GB, 256>>>(tg, out, out_size);  // 2
}